// round 1
// baseline (speedup 1.0000x reference)
#include <cuda_runtime.h>
#include <math.h>
#include <stdint.h>

#define B_ 8
#define C_ 192
#define H_ 128
#define W_ 128
#define HW_ 16384
#define HEADS_ 8
#define CPH_ 24          // channels per head
#define TEMP_INV 100.0f  // 1/temperature
#define EPS_ 1e-12f

// ---------------- scratch (device globals; no allocation allowed) ----------------
__device__ float g_o1[(size_t)B_ * C_ * HW_];     // out1 = conv(x1); later reused as t1
__device__ float g_o2[(size_t)B_ * C_ * HW_];     // out2 = conv(x2); later reused as t2
__device__ float g_fus[(size_t)B_ * C_ * HW_];    // fusion
__device__ float g_attn1[(size_t)B_ * HEADS_ * HW_];
__device__ float g_attn2[(size_t)B_ * HEADS_ * HW_];
__device__ float g_n1h[B_ * HEADS_ * H_];
__device__ float g_n2h[B_ * HEADS_ * H_];
__device__ float g_n1w[B_ * HEADS_ * W_];
__device__ float g_n2w[B_ * HEADS_ * W_];

// ---------------- conv1x1 GEMM: out[b,o,p] = act(sum_c W[o,c]*in[b,c,p] + bias[o]) (+res) ----
// grid: (HW/128, 192/96, B), block 256. BM=96 (out ch), BN=128 (pixels), BK=16.
__global__ __launch_bounds__(256) void conv_gemm_kernel(
    const float* __restrict__ in, const float* __restrict__ Wt,
    const float* __restrict__ bias, float* __restrict__ out,
    int act_gelu, const float* __restrict__ r1, const float* __restrict__ r2)
{
    __shared__ float sW[16][98];    // [kk][o]
    __shared__ float sX[16][132];   // [kk][pix]
    const int tid = threadIdx.x;
    const int tx = tid & 15, ty = tid >> 4;
    const int pix0 = blockIdx.x * 128;
    const int o0 = blockIdx.y * 96;
    const int b = blockIdx.z;
    const float* inb = in + (size_t)b * C_ * HW_;

    float acc[6][8];
#pragma unroll
    for (int i = 0; i < 6; i++)
#pragma unroll
        for (int j = 0; j < 8; j++) acc[i][j] = 0.f;

    for (int k0 = 0; k0 < C_; k0 += 16) {
#pragma unroll
        for (int r = 0; r < 6; r++) {
            int f = tid + 256 * r;          // 0..1535
            int o = f >> 4, kk = f & 15;
            sW[kk][o] = Wt[(o0 + o) * C_ + k0 + kk];
        }
#pragma unroll
        for (int r = 0; r < 2; r++) {
            int f4 = tid + 256 * r;         // 0..511
            int row = f4 >> 5, c4 = f4 & 31;
            float4 v = *(const float4*)(inb + (size_t)(k0 + row) * HW_ + pix0 + c4 * 4);
            *(float4*)&sX[row][c4 * 4] = v;
        }
        __syncthreads();
#pragma unroll
        for (int kk = 0; kk < 16; kk++) {
            float a[6], bb[8];
#pragma unroll
            for (int i = 0; i < 6; i++) a[i] = sW[kk][ty * 6 + i];
            float4 b0 = *(const float4*)&sX[kk][tx * 8];
            float4 b1 = *(const float4*)&sX[kk][tx * 8 + 4];
            bb[0] = b0.x; bb[1] = b0.y; bb[2] = b0.z; bb[3] = b0.w;
            bb[4] = b1.x; bb[5] = b1.y; bb[6] = b1.z; bb[7] = b1.w;
#pragma unroll
            for (int i = 0; i < 6; i++)
#pragma unroll
                for (int j = 0; j < 8; j++) acc[i][j] += a[i] * bb[j];
        }
        __syncthreads();
    }
#pragma unroll
    for (int i = 0; i < 6; i++) {
        int o = o0 + ty * 6 + i;
        float bv = bias[o];
        size_t base = ((size_t)b * C_ + o) * HW_ + pix0 + tx * 8;
#pragma unroll
        for (int j = 0; j < 8; j++) {
            float v = acc[i][j] + bv;
            if (act_gelu) v = 0.5f * v * (1.0f + erff(v * 0.70710678118654752f));
            if (r1) v += r1[base + j] + r2[base + j];
            out[base + j] = v;
        }
    }
}

// ---------------- norms: per (b,head): row norms over (cc,w) and col norms over (cc,h) ----
// grid: (B*HEADS, 2 sources), block 256.
__global__ __launch_bounds__(256) void norm_kernel(
    const float* __restrict__ o1, const float* __restrict__ o2,
    float* __restrict__ n1h, float* __restrict__ n1w,
    float* __restrict__ n2h, float* __restrict__ n2w)
{
    const int bh = blockIdx.x;       // b*8 + head
    const int src = blockIdx.y;
    const int tid = threadIdx.x;
    const float* base = (src ? o2 : o1) + ((size_t)(bh >> 3) * C_ + (bh & 7) * CPH_) * HW_;

    __shared__ float sRow[128];
    __shared__ float sColA[256];
    if (tid < 128) sRow[tid] = 0.f;
    __syncthreads();

    float colAcc = 0.f;
    // idx = cc*16384 + y*128 + x ; x = tid&127 is constant per thread; y constant per warp per iter
    for (int idx = tid; idx < CPH_ * HW_; idx += 256) {
        float v = base[idx];
        v *= v;
        colAcc += v;
        float rv = v;
#pragma unroll
        for (int s = 16; s >= 1; s >>= 1) rv += __shfl_xor_sync(0xffffffffu, rv, s);
        if ((tid & 31) == 0) {
            int y = (idx >> 7) & 127;
            atomicAdd(&sRow[y], rv);
        }
    }
    sColA[tid] = colAcc;
    __syncthreads();
    if (tid < 128) {
        float cs = sColA[tid] + sColA[tid + 128];
        float rs = sRow[tid];
        if (src) { n2h[bh * 128 + tid] = sqrtf(rs); n2w[bh * 128 + tid] = sqrtf(cs); }
        else     { n1h[bh * 128 + tid] = sqrtf(rs); n1w[bh * 128 + tid] = sqrtf(cs); }
    }
}

// ---------------- attention QK^T + scale + bias + softmax ----------------
// mode0: attn1[i,j] = softmax_j( (sum_ch S2 S1^T)/(n2h_i n1h_j T) + pbh )
// mode1: attn2[i,j] = softmax_j( (sum_ch S1^T S2)/(n1w_i n2w_j T) + pbw )
// grid: (B*HEADS, 2), block 256, 128x128 output per block, K=3072.
__global__ __launch_bounds__(256) void attn_kernel(
    const float* __restrict__ o1, const float* __restrict__ o2,
    const float* __restrict__ n1h, const float* __restrict__ n2h,
    const float* __restrict__ n1w, const float* __restrict__ n2w,
    const float* __restrict__ pbh, const float* __restrict__ pbw,
    float* __restrict__ attn1, float* __restrict__ attn2)
{
    __shared__ float sA[16][132];
    __shared__ float sB[16][132];
    const int bh = blockIdx.x;
    const int mode = blockIdx.y;
    const int hd = bh & 7;
    const int tid = threadIdx.x;
    const int tx = tid & 15, ty = tid >> 4;
    const float* S1 = o1 + ((size_t)(bh >> 3) * C_ + hd * CPH_) * HW_;
    const float* S2 = o2 + ((size_t)(bh >> 3) * C_ + hd * CPH_) * HW_;

    float acc[8][8];
#pragma unroll
    for (int i = 0; i < 8; i++)
#pragma unroll
        for (int j = 0; j < 8; j++) acc[i][j] = 0.f;

    for (int ch = 0; ch < CPH_; ch++) {
        const float* p1 = S1 + (size_t)ch * HW_;
        const float* p2 = S2 + (size_t)ch * HW_;
        for (int k0 = 0; k0 < 128; k0 += 16) {
            if (mode == 0) {
                // Gram over w: A[i][k]=S2[i][k], B[j][k]=S1[j][k] (transposed into shared)
#pragma unroll
                for (int r = 0; r < 2; r++) {
                    int f4 = tid + 256 * r;
                    int i = f4 >> 2, kq = f4 & 3;
                    float4 va = *(const float4*)(p2 + i * 128 + k0 + kq * 4);
                    float4 vb = *(const float4*)(p1 + i * 128 + k0 + kq * 4);
                    sA[kq * 4 + 0][i] = va.x; sA[kq * 4 + 1][i] = va.y;
                    sA[kq * 4 + 2][i] = va.z; sA[kq * 4 + 3][i] = va.w;
                    sB[kq * 4 + 0][i] = vb.x; sB[kq * 4 + 1][i] = vb.y;
                    sB[kq * 4 + 2][i] = vb.z; sB[kq * 4 + 3][i] = vb.w;
                }
            } else {
                // Gram over h: A[i][k]=S1[k][i], B[j][k]=S2[k][j] (direct rows)
#pragma unroll
                for (int r = 0; r < 2; r++) {
                    int f4 = tid + 256 * r;
                    int row = f4 >> 5, c4 = f4 & 31;
                    *(float4*)&sA[row][c4 * 4] = *(const float4*)(p1 + (k0 + row) * 128 + c4 * 4);
                    *(float4*)&sB[row][c4 * 4] = *(const float4*)(p2 + (k0 + row) * 128 + c4 * 4);
                }
            }
            __syncthreads();
#pragma unroll
            for (int kk = 0; kk < 16; kk++) {
                float4 a0 = *(const float4*)&sA[kk][ty * 8];
                float4 a1 = *(const float4*)&sA[kk][ty * 8 + 4];
                float4 b0 = *(const float4*)&sB[kk][tx * 8];
                float4 b1 = *(const float4*)&sB[kk][tx * 8 + 4];
                float a[8] = {a0.x, a0.y, a0.z, a0.w, a1.x, a1.y, a1.z, a1.w};
                float bb[8] = {b0.x, b0.y, b0.z, b0.w, b1.x, b1.y, b1.z, b1.w};
#pragma unroll
                for (int i = 0; i < 8; i++)
#pragma unroll
                    for (int j = 0; j < 8; j++) acc[i][j] += a[i] * bb[j];
            }
            __syncthreads();
        }
    }

    // scale + bias + row softmax (rows live on a 16-lane half-warp: lanes share ty)
    const float* nI = mode ? n1w : n2h;
    const float* nJ = mode ? n2w : n1h;
    const float bias = mode ? pbw[hd] : pbh[hd];
    float rinv[8], cinv[8];
#pragma unroll
    for (int r = 0; r < 8; r++) rinv[r] = 1.f / fmaxf(nI[bh * 128 + ty * 8 + r], EPS_);
#pragma unroll
    for (int c = 0; c < 8; c++) cinv[c] = 1.f / fmaxf(nJ[bh * 128 + tx * 8 + c], EPS_);

    float* attn = (mode ? attn2 : attn1) + (size_t)bh * HW_;
#pragma unroll
    for (int r = 0; r < 8; r++) {
        float l[8];
        float m = -1e30f;
#pragma unroll
        for (int c = 0; c < 8; c++) {
            l[c] = acc[r][c] * (rinv[r] * cinv[c] * TEMP_INV) + bias;
            m = fmaxf(m, l[c]);
        }
#pragma unroll
        for (int s = 8; s >= 1; s >>= 1) m = fmaxf(m, __shfl_xor_sync(0xffffffffu, m, s, 16));
        float sum = 0.f;
#pragma unroll
        for (int c = 0; c < 8; c++) { l[c] = expf(l[c] - m); sum += l[c]; }
#pragma unroll
        for (int s = 8; s >= 1; s >>= 1) sum += __shfl_xor_sync(0xffffffffu, sum, s, 16);
        float inv = 1.f / sum;
        int i = ty * 8 + r;
        float4 w0 = {l[0] * inv, l[1] * inv, l[2] * inv, l[3] * inv};
        float4 w1 = {l[4] * inv, l[5] * inv, l[6] * inv, l[7] * inv};
        *(float4*)(attn + i * 128 + tx * 8) = w0;
        *(float4*)(attn + i * 128 + tx * 8 + 4) = w1;
    }
}

// ---------------- AV + q-residual + gated fusion ----------------
// fusion[b,ch,y,x] = g*( (attn1@S1)[y,x] + S2[y,x]/n2h[y] )
//                  + (1-g)*( (S2@attn2^T)[y,x] + S1[y,x]/n1w[x] )
// grid: (C, B), block 256, 128x128 per block, two K=128 GEMMs.
__global__ __launch_bounds__(256) void av_fusion_kernel(
    const float* __restrict__ o1, const float* __restrict__ o2,
    const float* __restrict__ attn1, const float* __restrict__ attn2,
    const float* __restrict__ n2h, const float* __restrict__ n1w,
    const float* __restrict__ gate, float* __restrict__ fus)
{
    __shared__ float sA1[16][132];  // attn1[y][k] -> [k][y]
    __shared__ float sB1[16][132];  // S1[k][x]
    __shared__ float sA2[16][132];  // S2[y][k]   -> [k][y]
    __shared__ float sB2[16][132];  // attn2[x][k]-> [k][x]
    const int ch = blockIdx.x, b = blockIdx.y;
    const int hd = ch / CPH_;
    const int bh = b * 8 + hd;
    const int tid = threadIdx.x;
    const int tx = tid & 15, ty = tid >> 4;
    const float* S1 = o1 + ((size_t)b * C_ + ch) * HW_;
    const float* S2 = o2 + ((size_t)b * C_ + ch) * HW_;
    const float* A1 = attn1 + (size_t)bh * HW_;
    const float* A2 = attn2 + (size_t)bh * HW_;

    float acc1[8][8], acc2[8][8];
#pragma unroll
    for (int i = 0; i < 8; i++)
#pragma unroll
        for (int j = 0; j < 8; j++) { acc1[i][j] = 0.f; acc2[i][j] = 0.f; }

    for (int k0 = 0; k0 < 128; k0 += 16) {
#pragma unroll
        for (int r = 0; r < 2; r++) {
            int f4 = tid + 256 * r;
            int i = f4 >> 2, kq = f4 & 3;
            float4 va1 = *(const float4*)(A1 + i * 128 + k0 + kq * 4);
            float4 va2 = *(const float4*)(S2 + i * 128 + k0 + kq * 4);
            float4 vb2 = *(const float4*)(A2 + i * 128 + k0 + kq * 4);
#pragma unroll
            for (int e = 0; e < 4; e++) {
                ((&va1.x))[e] = ((&va1.x))[e];  // no-op to keep arrays addressable
            }
            sA1[kq * 4 + 0][i] = va1.x; sA1[kq * 4 + 1][i] = va1.y;
            sA1[kq * 4 + 2][i] = va1.z; sA1[kq * 4 + 3][i] = va1.w;
            sA2[kq * 4 + 0][i] = va2.x; sA2[kq * 4 + 1][i] = va2.y;
            sA2[kq * 4 + 2][i] = va2.z; sA2[kq * 4 + 3][i] = va2.w;
            sB2[kq * 4 + 0][i] = vb2.x; sB2[kq * 4 + 1][i] = vb2.y;
            sB2[kq * 4 + 2][i] = vb2.z; sB2[kq * 4 + 3][i] = vb2.w;
            int row = f4 >> 5, c4 = f4 & 31;
            *(float4*)&sB1[row][c4 * 4] = *(const float4*)(S1 + (k0 + row) * 128 + c4 * 4);
        }
        __syncthreads();
#pragma unroll
        for (int kk = 0; kk < 16; kk++) {
            float4 a10 = *(const float4*)&sA1[kk][ty * 8];
            float4 a11 = *(const float4*)&sA1[kk][ty * 8 + 4];
            float4 b10 = *(const float4*)&sB1[kk][tx * 8];
            float4 b11 = *(const float4*)&sB1[kk][tx * 8 + 4];
            float4 a20 = *(const float4*)&sA2[kk][ty * 8];
            float4 a21 = *(const float4*)&sA2[kk][ty * 8 + 4];
            float4 b20 = *(const float4*)&sB2[kk][tx * 8];
            float4 b21 = *(const float4*)&sB2[kk][tx * 8 + 4];
            float a1[8] = {a10.x, a10.y, a10.z, a10.w, a11.x, a11.y, a11.z, a11.w};
            float b1[8] = {b10.x, b10.y, b10.z, b10.w, b11.x, b11.y, b11.z, b11.w};
            float a2[8] = {a20.x, a20.y, a20.z, a20.w, a21.x, a21.y, a21.z, a21.w};
            float b2[8] = {b20.x, b20.y, b20.z, b20.w, b21.x, b21.y, b21.z, b21.w};
#pragma unroll
            for (int i = 0; i < 8; i++)
#pragma unroll
                for (int j = 0; j < 8; j++) {
                    acc1[i][j] += a1[i] * b1[j];
                    acc2[i][j] += a2[i] * b2[j];
                }
        }
        __syncthreads();
    }

    const float g = 1.f / (1.f + expf(-gate[0]));
    float invy[8], invx[8];
#pragma unroll
    for (int r = 0; r < 8; r++) invy[r] = 1.f / fmaxf(n2h[bh * 128 + ty * 8 + r], EPS_);
#pragma unroll
    for (int c = 0; c < 8; c++) invx[c] = 1.f / fmaxf(n1w[bh * 128 + tx * 8 + c], EPS_);

    float* fout = fus + ((size_t)b * C_ + ch) * HW_;
#pragma unroll
    for (int r = 0; r < 8; r++) {
        int y = ty * 8 + r;
        float o[8];
#pragma unroll
        for (int c = 0; c < 8; c++) {
            int x = tx * 8 + c;
            float v2 = S2[y * 128 + x];
            float v1 = S1[y * 128 + x];
            o[c] = g * (acc1[r][c] + v2 * invy[r]) + (1.f - g) * (acc2[r][c] + v1 * invx[c]);
        }
        float4 w0 = {o[0], o[1], o[2], o[3]};
        float4 w1 = {o[4], o[5], o[6], o[7]};
        *(float4*)(fout + y * 128 + tx * 8) = w0;
        *(float4*)(fout + y * 128 + tx * 8 + 4) = w1;
    }
}

// ---------------- host launcher ----------------
extern "C" void kernel_launch(void* const* d_in, const int* in_sizes, int n_in,
                              void* d_out, int out_size)
{
    const float* x1  = (const float*)d_in[0];
    const float* x2  = (const float*)d_in[1];
    const float* Wp  = (const float*)d_in[2];
    const float* bp  = (const float*)d_in[3];
    const float* gate= (const float*)d_in[4];
    const float* pbh = (const float*)d_in[5];
    const float* pbw = (const float*)d_in[6];
    const float* Wm1 = (const float*)d_in[7];
    const float* bm1 = (const float*)d_in[8];
    const float* Wm2 = (const float*)d_in[9];
    const float* bm2 = (const float*)d_in[10];
    float* out = (float*)d_out;

    float *p_o1, *p_o2, *p_fus, *p_a1, *p_a2, *p_n1h, *p_n2h, *p_n1w, *p_n2w;
    cudaGetSymbolAddress((void**)&p_o1, g_o1);
    cudaGetSymbolAddress((void**)&p_o2, g_o2);
    cudaGetSymbolAddress((void**)&p_fus, g_fus);
    cudaGetSymbolAddress((void**)&p_a1, g_attn1);
    cudaGetSymbolAddress((void**)&p_a2, g_attn2);
    cudaGetSymbolAddress((void**)&p_n1h, g_n1h);
    cudaGetSymbolAddress((void**)&p_n2h, g_n2h);
    cudaGetSymbolAddress((void**)&p_n1w, g_n1w);
    cudaGetSymbolAddress((void**)&p_n2w, g_n2w);

    dim3 convGrid(HW_ / 128, C_ / 96, B_);

    // out1 = conv(x1), out2 = conv(x2)
    conv_gemm_kernel<<<convGrid, 256>>>(x1, Wp, bp, p_o1, 0, nullptr, nullptr);
    conv_gemm_kernel<<<convGrid, 256>>>(x2, Wp, bp, p_o2, 0, nullptr, nullptr);

    // token norms
    norm_kernel<<<dim3(B_ * HEADS_, 2), 256>>>(p_o1, p_o2, p_n1h, p_n1w, p_n2h, p_n2w);

    // attention matrices (QK^T + softmax)
    attn_kernel<<<dim3(B_ * HEADS_, 2), 256>>>(p_o1, p_o2, p_n1h, p_n2h, p_n1w, p_n2w,
                                               pbh, pbw, p_a1, p_a2);

    // AV + residual-q + gated fusion
    av_fusion_kernel<<<dim3(C_, B_), 256>>>(p_o1, p_o2, p_a1, p_a2, p_n2h, p_n1w, gate, p_fus);

    // out5 = conv(fusion, W_proj) -> reuse g_o1
    conv_gemm_kernel<<<convGrid, 256>>>(p_fus, Wp, bp, p_o1, 0, nullptr, nullptr);
    // t = gelu(conv(out5, W_m1)) -> reuse g_o2
    conv_gemm_kernel<<<convGrid, 256>>>(p_o1, Wm1, bm1, p_o2, 1, nullptr, nullptr);
    // out = conv(t, W_m2) + x1 + x2
    conv_gemm_kernel<<<convGrid, 256>>>(p_o2, Wm2, bm2, out, 0, x1, x2);

    (void)in_sizes; (void)n_in; (void)out_size;
}

// round 3
// speedup vs baseline: 1.2395x; 1.2395x over previous
#include <cuda_runtime.h>
#include <math.h>
#include <stdint.h>

#define B_ 8
#define C_ 192
#define H_ 128
#define W_ 128
#define HW_ 16384
#define HEADS_ 8
#define CPH_ 24
#define TEMP_INV 100.0f
#define EPS_ 1e-12f

#define NPIX_ (B_ * HW_)          // 131072
#define NTILES_ (NPIX_ / 128)     // 1024
#define TILE_ELEMS (128 * C_)     // 24576 floats per tile (channel-last)

// ---------------- scratch ----------------
__device__ float g_o1[(size_t)B_ * C_ * HW_];
__device__ float g_o2[(size_t)B_ * C_ * HW_];
__device__ float g_fus[(size_t)B_ * C_ * HW_];
__device__ float g_cl[(size_t)NPIX_ * C_];      // channel-last staging
__device__ float g_attn1[(size_t)B_ * HEADS_ * HW_];
__device__ float g_attn2[(size_t)B_ * HEADS_ * HW_];
__device__ float g_n1h[B_ * HEADS_ * H_];
__device__ float g_n2h[B_ * HEADS_ * H_];
__device__ float g_n1w[B_ * HEADS_ * W_];
__device__ float g_n2w[B_ * HEADS_ * W_];

__device__ __forceinline__ float to_tf32(float x) {
    uint32_t u; asm("cvt.rna.tf32.f32 %0, %1;" : "=r"(u) : "f"(x));
    return __uint_as_float(u);
}

__device__ __forceinline__ void mma_tf32(float* c, const uint32_t* a, const uint32_t* b) {
    asm volatile(
        "mma.sync.aligned.m16n8k8.row.col.f32.tf32.tf32.f32 "
        "{%0,%1,%2,%3}, {%4,%5,%6,%7}, {%8,%9}, {%0,%1,%2,%3};"
        : "+f"(c[0]), "+f"(c[1]), "+f"(c[2]), "+f"(c[3])
        : "r"(a[0]), "r"(a[1]), "r"(a[2]), "r"(a[3]), "r"(b[0]), "r"(b[1]));
}

// ---------------- transpose: channel-first [b,c,p] -> channel-last [bp, c], tf32-rounded ----
__global__ __launch_bounds__(256) void transpose_cf_cl_kernel(
    const float* __restrict__ in, float* __restrict__ out)
{
    __shared__ float t[32][33];
    const int b = blockIdx.z;
    const int p0 = blockIdx.x * 32;
    const int c0 = blockIdx.y * 32;
    const int tx = threadIdx.x, ty = threadIdx.y;
    const float* ib = in + (size_t)b * C_ * HW_;
    float* ob = out + (size_t)b * HW_ * C_;
#pragma unroll
    for (int i = ty; i < 32; i += 8)
        t[i][tx] = ib[(size_t)(c0 + i) * HW_ + p0 + tx];
    __syncthreads();
#pragma unroll
    for (int i = ty; i < 32; i += 8)
        ob[(size_t)(p0 + i) * C_ + c0 + tx] = to_tf32(t[tx][i]);
}

// ---------------- conv1x1 via mma.sync tf32 ----------------
// A: channel-last [NPIX, 192] (tf32-rounded). W: [192 out, 192 in] row-major (rounded on load).
// Per CTA: 128 pixels x 192 outs, K = 6 chunks of 32. 8 warps: 2(m) x 4(n), warp tile 64x48.
// flags: bit0 = gelu, bit1 = channel-last output (tf32-rounded).
#define SAS 36
#define SW_OFF (128 * SAS)              // sW starts here (floats)
#define SMEM_FLOATS (128 * 196)         // epilogue staging dominates
#define SMEM_BYTES (SMEM_FLOATS * 4)    // 100352

__global__ __launch_bounds__(256, 1) void conv_mma_kernel(
    const float* __restrict__ Acl, const float* __restrict__ Wt,
    const float* __restrict__ bias, float* __restrict__ out,
    int flags, const float* __restrict__ r1, const float* __restrict__ r2)
{
    extern __shared__ float sm[];
    float* sA = sm;              // [128][36]
    float* sW = sm + SW_OFF;     // [192][36]
    const int tid = threadIdx.x;
    const int lane = tid & 31;
    const int g = lane >> 2;         // group id 0..7
    const int tig = lane & 3;        // thread in group 0..3
    const int wid = tid >> 5;
    const int mbase = (wid & 1) * 64;
    const int nbase = (wid >> 1) * 48;
    const int t = blockIdx.x;
    const float* Arow = Acl + (size_t)t * TILE_ELEMS;

    float c[4][6][4];
#pragma unroll
    for (int mt = 0; mt < 4; mt++)
#pragma unroll
        for (int nt = 0; nt < 6; nt++)
#pragma unroll
            for (int r = 0; r < 4; r++) c[mt][nt][r] = 0.f;

    for (int kc = 0; kc < 6; kc++) {
        // stage A chunk [128][32]
#pragma unroll
        for (int r = 0; r < 4; r++) {
            int f = tid + 256 * r;           // 1024 float4
            int pix = f >> 3, c4 = f & 7;
            float4 v = *(const float4*)(Arow + (size_t)pix * C_ + kc * 32 + c4 * 4);
            *(float4*)&sA[pix * SAS + c4 * 4] = v;
        }
        // stage W chunk [192][32], tf32-rounded
#pragma unroll
        for (int r = 0; r < 6; r++) {
            int f = tid + 256 * r;           // 1536 float4
            int o = f >> 3, c4 = f & 7;
            float4 v = *(const float4*)(Wt + (size_t)o * C_ + kc * 32 + c4 * 4);
            v.x = to_tf32(v.x); v.y = to_tf32(v.y);
            v.z = to_tf32(v.z); v.w = to_tf32(v.w);
            *(float4*)&sW[o * SAS + c4 * 4] = v;
        }
        __syncthreads();
#pragma unroll
        for (int kk = 0; kk < 4; kk++) {
            const int k0 = kk * 8 + tig;
            uint32_t a[4][4], b[6][2];
#pragma unroll
            for (int mt = 0; mt < 4; mt++) {
                int row = mbase + mt * 16 + g;
                a[mt][0] = __float_as_uint(sA[row * SAS + k0]);
                a[mt][1] = __float_as_uint(sA[(row + 8) * SAS + k0]);
                a[mt][2] = __float_as_uint(sA[row * SAS + k0 + 4]);
                a[mt][3] = __float_as_uint(sA[(row + 8) * SAS + k0 + 4]);
            }
#pragma unroll
            for (int nt = 0; nt < 6; nt++) {
                int col = nbase + nt * 8 + g;
                b[nt][0] = __float_as_uint(sW[col * SAS + k0]);
                b[nt][1] = __float_as_uint(sW[col * SAS + k0 + 4]);
            }
#pragma unroll
            for (int mt = 0; mt < 4; mt++)
#pragma unroll
                for (int nt = 0; nt < 6; nt++)
                    mma_tf32(c[mt][nt], a[mt], b[nt]);
        }
        __syncthreads();
    }

    const int gelu = flags & 1;
    // bias values for this thread's 12 output columns
    float bv[6][2];
#pragma unroll
    for (int nt = 0; nt < 6; nt++) {
        int o = nbase + nt * 8 + 2 * tig;
        bv[nt][0] = __ldg(&bias[o]);
        bv[nt][1] = __ldg(&bias[o + 1]);
    }

    if (flags & 2) {
        // channel-last output via smem staging, tf32-rounded
        float* sO = sm;   // [128][196]
#pragma unroll
        for (int mt = 0; mt < 4; mt++) {
            int row0 = mbase + mt * 16 + g;
#pragma unroll
            for (int nt = 0; nt < 6; nt++) {
                int o = nbase + nt * 8 + 2 * tig;
#pragma unroll
                for (int half = 0; half < 2; half++) {
                    int row = row0 + half * 8;
                    float v0 = c[mt][nt][half * 2 + 0] + bv[nt][0];
                    float v1 = c[mt][nt][half * 2 + 1] + bv[nt][1];
                    if (gelu) {
                        v0 = 0.5f * v0 * (1.0f + erff(v0 * 0.70710678118654752f));
                        v1 = 0.5f * v1 * (1.0f + erff(v1 * 0.70710678118654752f));
                    }
                    float2 w = {to_tf32(v0), to_tf32(v1)};
                    *(float2*)&sO[row * 196 + o] = w;
                }
            }
        }
        __syncthreads();
        float* ob = out + (size_t)t * TILE_ELEMS;
#pragma unroll
        for (int r = 0; r < 24; r++) {
            int f = tid + 256 * r;           // 6144 float4
            int pix = f / 48, c4 = f % 48;
            *(float4*)(ob + (size_t)pix * C_ + c4 * 4) = *(float4*)&sO[pix * 196 + c4 * 4];
        }
    } else {
        // channel-first output, optional x1+x2 residual
        const int pg0 = t << 7;
        const int b = pg0 >> 14;
        const int p0 = pg0 & (HW_ - 1);
#pragma unroll
        for (int mt = 0; mt < 4; mt++) {
            int row0 = mbase + mt * 16 + g;
#pragma unroll
            for (int nt = 0; nt < 6; nt++) {
                int o = nbase + nt * 8 + 2 * tig;
#pragma unroll
                for (int half = 0; half < 2; half++) {
                    int row = row0 + half * 8;
#pragma unroll
                    for (int cc = 0; cc < 2; cc++) {
                        float v = c[mt][nt][half * 2 + cc] + bv[nt][cc];
                        if (gelu) v = 0.5f * v * (1.0f + erff(v * 0.70710678118654752f));
                        size_t idx = ((size_t)(b * C_ + o + cc) << 14) + p0 + row;
                        if (r1) v += __ldg(&r1[idx]) + __ldg(&r2[idx]);
                        out[idx] = v;
                    }
                }
            }
        }
    }
}

// ---------------- norms ----------------
__global__ __launch_bounds__(256) void norm_kernel(
    const float* __restrict__ o1, const float* __restrict__ o2,
    float* __restrict__ n1h, float* __restrict__ n1w,
    float* __restrict__ n2h, float* __restrict__ n2w)
{
    const int bh = blockIdx.x;
    const int src = blockIdx.y;
    const int tid = threadIdx.x;
    const float* base = (src ? o2 : o1) + ((size_t)(bh >> 3) * C_ + (bh & 7) * CPH_) * HW_;

    __shared__ float sRow[128];
    __shared__ float sColA[256];
    if (tid < 128) sRow[tid] = 0.f;
    __syncthreads();

    float colAcc = 0.f;
    for (int idx = tid; idx < CPH_ * HW_; idx += 256) {
        float v = base[idx];
        v *= v;
        colAcc += v;
        float rv = v;
#pragma unroll
        for (int s = 16; s >= 1; s >>= 1) rv += __shfl_xor_sync(0xffffffffu, rv, s);
        if ((tid & 31) == 0) atomicAdd(&sRow[(idx >> 7) & 127], rv);
    }
    sColA[tid] = colAcc;
    __syncthreads();
    if (tid < 128) {
        float cs = sColA[tid] + sColA[tid + 128];
        float rs = sRow[tid];
        if (src) { n2h[bh * 128 + tid] = sqrtf(rs); n2w[bh * 128 + tid] = sqrtf(cs); }
        else     { n1h[bh * 128 + tid] = sqrtf(rs); n1w[bh * 128 + tid] = sqrtf(cs); }
    }
}

// ---------------- attention QK^T + softmax (fp32) ----------------
__global__ __launch_bounds__(256) void attn_kernel(
    const float* __restrict__ o1, const float* __restrict__ o2,
    const float* __restrict__ n1h, const float* __restrict__ n2h,
    const float* __restrict__ n1w, const float* __restrict__ n2w,
    const float* __restrict__ pbh, const float* __restrict__ pbw,
    float* __restrict__ attn1, float* __restrict__ attn2)
{
    __shared__ float sA[16][132];
    __shared__ float sB[16][132];
    const int bh = blockIdx.x;
    const int mode = blockIdx.y;
    const int hd = bh & 7;
    const int tid = threadIdx.x;
    const int tx = tid & 15, ty = tid >> 4;
    const float* S1 = o1 + ((size_t)(bh >> 3) * C_ + hd * CPH_) * HW_;
    const float* S2 = o2 + ((size_t)(bh >> 3) * C_ + hd * CPH_) * HW_;

    float acc[8][8];
#pragma unroll
    for (int i = 0; i < 8; i++)
#pragma unroll
        for (int j = 0; j < 8; j++) acc[i][j] = 0.f;

    for (int ch = 0; ch < CPH_; ch++) {
        const float* p1 = S1 + (size_t)ch * HW_;
        const float* p2 = S2 + (size_t)ch * HW_;
        for (int k0 = 0; k0 < 128; k0 += 16) {
            if (mode == 0) {
#pragma unroll
                for (int r = 0; r < 2; r++) {
                    int f4 = tid + 256 * r;
                    int i = f4 >> 2, kq = f4 & 3;
                    float4 va = *(const float4*)(p2 + i * 128 + k0 + kq * 4);
                    float4 vb = *(const float4*)(p1 + i * 128 + k0 + kq * 4);
                    sA[kq * 4 + 0][i] = va.x; sA[kq * 4 + 1][i] = va.y;
                    sA[kq * 4 + 2][i] = va.z; sA[kq * 4 + 3][i] = va.w;
                    sB[kq * 4 + 0][i] = vb.x; sB[kq * 4 + 1][i] = vb.y;
                    sB[kq * 4 + 2][i] = vb.z; sB[kq * 4 + 3][i] = vb.w;
                }
            } else {
#pragma unroll
                for (int r = 0; r < 2; r++) {
                    int f4 = tid + 256 * r;
                    int row = f4 >> 5, c4 = f4 & 31;
                    *(float4*)&sA[row][c4 * 4] = *(const float4*)(p1 + (k0 + row) * 128 + c4 * 4);
                    *(float4*)&sB[row][c4 * 4] = *(const float4*)(p2 + (k0 + row) * 128 + c4 * 4);
                }
            }
            __syncthreads();
#pragma unroll
            for (int kk = 0; kk < 16; kk++) {
                float4 a0 = *(const float4*)&sA[kk][ty * 8];
                float4 a1 = *(const float4*)&sA[kk][ty * 8 + 4];
                float4 b0 = *(const float4*)&sB[kk][tx * 8];
                float4 b1 = *(const float4*)&sB[kk][tx * 8 + 4];
                float a[8] = {a0.x, a0.y, a0.z, a0.w, a1.x, a1.y, a1.z, a1.w};
                float bb[8] = {b0.x, b0.y, b0.z, b0.w, b1.x, b1.y, b1.z, b1.w};
#pragma unroll
                for (int i = 0; i < 8; i++)
#pragma unroll
                    for (int j = 0; j < 8; j++) acc[i][j] += a[i] * bb[j];
            }
            __syncthreads();
        }
    }

    const float* nI = mode ? n1w : n2h;
    const float* nJ = mode ? n2w : n1h;
    const float bias = mode ? pbw[hd] : pbh[hd];
    float rinv[8], cinv[8];
#pragma unroll
    for (int r = 0; r < 8; r++) rinv[r] = 1.f / fmaxf(nI[bh * 128 + ty * 8 + r], EPS_);
#pragma unroll
    for (int c = 0; c < 8; c++) cinv[c] = 1.f / fmaxf(nJ[bh * 128 + tx * 8 + c], EPS_);

    float* attn = (mode ? attn2 : attn1) + (size_t)bh * HW_;
#pragma unroll
    for (int r = 0; r < 8; r++) {
        float l[8];
        float m = -1e30f;
#pragma unroll
        for (int c = 0; c < 8; c++) {
            l[c] = acc[r][c] * (rinv[r] * cinv[c] * TEMP_INV) + bias;
            m = fmaxf(m, l[c]);
        }
#pragma unroll
        for (int s = 8; s >= 1; s >>= 1) m = fmaxf(m, __shfl_xor_sync(0xffffffffu, m, s, 16));
        float sum = 0.f;
#pragma unroll
        for (int c = 0; c < 8; c++) { l[c] = expf(l[c] - m); sum += l[c]; }
#pragma unroll
        for (int s = 8; s >= 1; s >>= 1) sum += __shfl_xor_sync(0xffffffffu, sum, s, 16);
        float inv = 1.f / sum;
        int i = ty * 8 + r;
        float4 w0 = {l[0] * inv, l[1] * inv, l[2] * inv, l[3] * inv};
        float4 w1 = {l[4] * inv, l[5] * inv, l[6] * inv, l[7] * inv};
        *(float4*)(attn + i * 128 + tx * 8) = w0;
        *(float4*)(attn + i * 128 + tx * 8 + 4) = w1;
    }
}

// ---------------- AV + q-residual + gated fusion ----------------
__global__ __launch_bounds__(256) void av_fusion_kernel(
    const float* __restrict__ o1, const float* __restrict__ o2,
    const float* __restrict__ attn1, const float* __restrict__ attn2,
    const float* __restrict__ n2h, const float* __restrict__ n1w,
    const float* __restrict__ gate, float* __restrict__ fus)
{
    __shared__ float sA1[16][132];
    __shared__ float sB1[16][132];
    __shared__ float sA2[16][132];
    __shared__ float sB2[16][132];
    const int ch = blockIdx.x, b = blockIdx.y;
    const int hd = ch / CPH_;
    const int bh = b * 8 + hd;
    const int tid = threadIdx.x;
    const int tx = tid & 15, ty = tid >> 4;
    const float* S1 = o1 + ((size_t)b * C_ + ch) * HW_;
    const float* S2 = o2 + ((size_t)b * C_ + ch) * HW_;
    const float* A1 = attn1 + (size_t)bh * HW_;
    const float* A2 = attn2 + (size_t)bh * HW_;

    float acc1[8][8], acc2[8][8];
#pragma unroll
    for (int i = 0; i < 8; i++)
#pragma unroll
        for (int j = 0; j < 8; j++) { acc1[i][j] = 0.f; acc2[i][j] = 0.f; }

    for (int k0 = 0; k0 < 128; k0 += 16) {
#pragma unroll
        for (int r = 0; r < 2; r++) {
            int f4 = tid + 256 * r;
            int i = f4 >> 2, kq = f4 & 3;
            float4 va1 = *(const float4*)(A1 + i * 128 + k0 + kq * 4);
            float4 va2 = *(const float4*)(S2 + i * 128 + k0 + kq * 4);
            float4 vb2 = *(const float4*)(A2 + i * 128 + k0 + kq * 4);
            sA1[kq * 4 + 0][i] = va1.x; sA1[kq * 4 + 1][i] = va1.y;
            sA1[kq * 4 + 2][i] = va1.z; sA1[kq * 4 + 3][i] = va1.w;
            sA2[kq * 4 + 0][i] = va2.x; sA2[kq * 4 + 1][i] = va2.y;
            sA2[kq * 4 + 2][i] = va2.z; sA2[kq * 4 + 3][i] = va2.w;
            sB2[kq * 4 + 0][i] = vb2.x; sB2[kq * 4 + 1][i] = vb2.y;
            sB2[kq * 4 + 2][i] = vb2.z; sB2[kq * 4 + 3][i] = vb2.w;
            int row = f4 >> 5, c4 = f4 & 31;
            *(float4*)&sB1[row][c4 * 4] = *(const float4*)(S1 + (k0 + row) * 128 + c4 * 4);
        }
        __syncthreads();
#pragma unroll
        for (int kk = 0; kk < 16; kk++) {
            float4 a10 = *(const float4*)&sA1[kk][ty * 8];
            float4 a11 = *(const float4*)&sA1[kk][ty * 8 + 4];
            float4 b10 = *(const float4*)&sB1[kk][tx * 8];
            float4 b11 = *(const float4*)&sB1[kk][tx * 8 + 4];
            float4 a20 = *(const float4*)&sA2[kk][ty * 8];
            float4 a21 = *(const float4*)&sA2[kk][ty * 8 + 4];
            float4 b20 = *(const float4*)&sB2[kk][tx * 8];
            float4 b21 = *(const float4*)&sB2[kk][tx * 8 + 4];
            float a1[8] = {a10.x, a10.y, a10.z, a10.w, a11.x, a11.y, a11.z, a11.w};
            float b1[8] = {b10.x, b10.y, b10.z, b10.w, b11.x, b11.y, b11.z, b11.w};
            float a2[8] = {a20.x, a20.y, a20.z, a20.w, a21.x, a21.y, a21.z, a21.w};
            float b2[8] = {b20.x, b20.y, b20.z, b20.w, b21.x, b21.y, b21.z, b21.w};
#pragma unroll
            for (int i = 0; i < 8; i++)
#pragma unroll
                for (int j = 0; j < 8; j++) {
                    acc1[i][j] += a1[i] * b1[j];
                    acc2[i][j] += a2[i] * b2[j];
                }
        }
        __syncthreads();
    }

    const float g = 1.f / (1.f + expf(-gate[0]));
    float invy[8], invx[8];
#pragma unroll
    for (int r = 0; r < 8; r++) invy[r] = 1.f / fmaxf(n2h[bh * 128 + ty * 8 + r], EPS_);
#pragma unroll
    for (int c = 0; c < 8; c++) invx[c] = 1.f / fmaxf(n1w[bh * 128 + tx * 8 + c], EPS_);

    float* fout = fus + ((size_t)b * C_ + ch) * HW_;
#pragma unroll
    for (int r = 0; r < 8; r++) {
        int y = ty * 8 + r;
        float o[8];
#pragma unroll
        for (int c = 0; c < 8; c++) {
            int x = tx * 8 + c;
            float v2 = S2[y * 128 + x];
            float v1 = S1[y * 128 + x];
            o[c] = g * (acc1[r][c] + v2 * invy[r]) + (1.f - g) * (acc2[r][c] + v1 * invx[c]);
        }
        float4 w0 = {o[0], o[1], o[2], o[3]};
        float4 w1 = {o[4], o[5], o[6], o[7]};
        *(float4*)(fout + y * 128 + tx * 8) = w0;
        *(float4*)(fout + y * 128 + tx * 8 + 4) = w1;
    }
}

// ---------------- host launcher ----------------
extern "C" void kernel_launch(void* const* d_in, const int* in_sizes, int n_in,
                              void* d_out, int out_size)
{
    const float* x1  = (const float*)d_in[0];
    const float* x2  = (const float*)d_in[1];
    const float* Wp  = (const float*)d_in[2];
    const float* bp  = (const float*)d_in[3];
    const float* gate= (const float*)d_in[4];
    const float* pbh = (const float*)d_in[5];
    const float* pbw = (const float*)d_in[6];
    const float* Wm1 = (const float*)d_in[7];
    const float* bm1 = (const float*)d_in[8];
    const float* Wm2 = (const float*)d_in[9];
    const float* bm2 = (const float*)d_in[10];
    float* out = (float*)d_out;

    float *p_o1, *p_o2, *p_fus, *p_cl, *p_a1, *p_a2, *p_n1h, *p_n2h, *p_n1w, *p_n2w;
    cudaGetSymbolAddress((void**)&p_o1, g_o1);
    cudaGetSymbolAddress((void**)&p_o2, g_o2);
    cudaGetSymbolAddress((void**)&p_fus, g_fus);
    cudaGetSymbolAddress((void**)&p_cl, g_cl);
    cudaGetSymbolAddress((void**)&p_a1, g_attn1);
    cudaGetSymbolAddress((void**)&p_a2, g_attn2);
    cudaGetSymbolAddress((void**)&p_n1h, g_n1h);
    cudaGetSymbolAddress((void**)&p_n2h, g_n2h);
    cudaGetSymbolAddress((void**)&p_n1w, g_n1w);
    cudaGetSymbolAddress((void**)&p_n2w, g_n2w);

    cudaFuncSetAttribute(conv_mma_kernel, cudaFuncAttributeMaxDynamicSharedMemorySize, SMEM_BYTES);

    dim3 tGrid(HW_ / 32, C_ / 32, B_);
    dim3 tBlk(32, 8);

    // out1 = conv(x1)  -> channel-first (feeds attention)
    transpose_cf_cl_kernel<<<tGrid, tBlk>>>(x1, p_cl);
    conv_mma_kernel<<<NTILES_, 256, SMEM_BYTES>>>(p_cl, Wp, bp, p_o1, 0, nullptr, nullptr);
    // out2 = conv(x2)  -> channel-first
    transpose_cf_cl_kernel<<<tGrid, tBlk>>>(x2, p_cl);
    conv_mma_kernel<<<NTILES_, 256, SMEM_BYTES>>>(p_cl, Wp, bp, p_o2, 0, nullptr, nullptr);

    norm_kernel<<<dim3(B_ * HEADS_, 2), 256>>>(p_o1, p_o2, p_n1h, p_n1w, p_n2h, p_n2w);
    attn_kernel<<<dim3(B_ * HEADS_, 2), 256>>>(p_o1, p_o2, p_n1h, p_n2h, p_n1w, p_n2w,
                                               pbh, pbw, p_a1, p_a2);
    av_fusion_kernel<<<dim3(C_, B_), 256>>>(p_o1, p_o2, p_a1, p_a2, p_n2h, p_n1w, gate, p_fus);

    // out5 = conv(fusion, W_proj) -> channel-last (feeds next conv)
    transpose_cf_cl_kernel<<<tGrid, tBlk>>>(p_fus, p_cl);
    conv_mma_kernel<<<NTILES_, 256, SMEM_BYTES>>>(p_cl, Wp, bp, p_o1, 2, nullptr, nullptr);
    // t = gelu(conv(out5, W_m1)) -> channel-last
    conv_mma_kernel<<<NTILES_, 256, SMEM_BYTES>>>(p_o1, Wm1, bm1, p_o2, 3, nullptr, nullptr);
    // out = conv(t, W_m2) + x1 + x2 -> channel-first
    conv_mma_kernel<<<NTILES_, 256, SMEM_BYTES>>>(p_o2, Wm2, bm2, out, 0, x1, x2);

    (void)in_sizes; (void)n_in; (void)out_size;
}

// round 4
// speedup vs baseline: 1.5028x; 1.2124x over previous
#include <cuda_runtime.h>
#include <math.h>
#include <stdint.h>

#define B_ 8
#define C_ 192
#define H_ 128
#define W_ 128
#define HW_ 16384
#define HEADS_ 8
#define CPH_ 24
#define TEMP_INV 100.0f
#define EPS_ 1e-12f

#define NPIX_ (B_ * HW_)          // 131072
#define NTILES_ (NPIX_ / 128)     // 1024
#define TILE_ELEMS (128 * C_)

// ---------------- scratch ----------------
__device__ float g_o1[(size_t)B_ * C_ * HW_];
__device__ float g_o2[(size_t)B_ * C_ * HW_];
__device__ float g_o1t[(size_t)B_ * C_ * HW_];  // [b][c][x][y]
__device__ float g_o2t[(size_t)B_ * C_ * HW_];
__device__ float g_fus[(size_t)B_ * C_ * HW_];
__device__ float g_cl[(size_t)NPIX_ * C_];
__device__ float g_attn1[(size_t)B_ * HEADS_ * HW_];
__device__ float g_attn2[(size_t)B_ * HEADS_ * HW_];
__device__ float g_n1h[B_ * HEADS_ * H_];
__device__ float g_n2h[B_ * HEADS_ * H_];
__device__ float g_n1w[B_ * HEADS_ * W_];
__device__ float g_n2w[B_ * HEADS_ * W_];

__device__ __forceinline__ float to_tf32(float x) {
    uint32_t u; asm("cvt.rna.tf32.f32 %0, %1;" : "=r"(u) : "f"(x));
    return __uint_as_float(u);
}
__device__ __forceinline__ float4 to_tf32_4(float4 v) {
    v.x = to_tf32(v.x); v.y = to_tf32(v.y); v.z = to_tf32(v.z); v.w = to_tf32(v.w);
    return v;
}

__device__ __forceinline__ void mma_tf32(float* c, const uint32_t* a, const uint32_t* b) {
    asm volatile(
        "mma.sync.aligned.m16n8k8.row.col.f32.tf32.tf32.f32 "
        "{%0,%1,%2,%3}, {%4,%5,%6,%7}, {%8,%9}, {%0,%1,%2,%3};"
        : "+f"(c[0]), "+f"(c[1]), "+f"(c[2]), "+f"(c[3])
        : "r"(a[0]), "r"(a[1]), "r"(a[2]), "r"(a[3]), "r"(b[0]), "r"(b[1]));
}

// ---------------- transpose: channel-first -> channel-last, tf32-rounded ----
__global__ __launch_bounds__(256) void transpose_cf_cl_kernel(
    const float* __restrict__ in, float* __restrict__ out)
{
    __shared__ float t[32][33];
    const int b = blockIdx.z;
    const int p0 = blockIdx.x * 32;
    const int c0 = blockIdx.y * 32;
    const int tx = threadIdx.x, ty = threadIdx.y;
    const float* ib = in + (size_t)b * C_ * HW_;
    float* ob = out + (size_t)b * HW_ * C_;
#pragma unroll
    for (int i = ty; i < 32; i += 8)
        t[i][tx] = ib[(size_t)(c0 + i) * HW_ + p0 + tx];
    __syncthreads();
#pragma unroll
    for (int i = ty; i < 32; i += 8)
        ob[(size_t)(p0 + i) * C_ + c0 + tx] = to_tf32(t[tx][i]);
}

// ---------------- repack: per (b,c) [y][x] -> [x][y] ----------------
__global__ __launch_bounds__(256) void repack_kernel(
    const float* __restrict__ in, float* __restrict__ out)
{
    __shared__ float t[32][33];
    const int c = blockIdx.y, b = blockIdx.z;
    const int x0 = (blockIdx.x & 3) * 32, y0 = (blockIdx.x >> 2) * 32;
    const int tx = threadIdx.x, ty = threadIdx.y;
    const float* ib = in + ((size_t)b * C_ + c) * HW_;
    float* ob = out + ((size_t)b * C_ + c) * HW_;
#pragma unroll
    for (int i = ty; i < 32; i += 8)
        t[i][tx] = ib[(y0 + i) * 128 + x0 + tx];
    __syncthreads();
#pragma unroll
    for (int i = ty; i < 32; i += 8)
        ob[(x0 + i) * 128 + y0 + tx] = t[tx][i];
}

// ---------------- conv1x1 via mma.sync tf32 (unchanged from R3) ----------------
#define SAS 36
#define SW_OFF (128 * SAS)
#define SMEM_FLOATS (128 * 196)
#define SMEM_BYTES (SMEM_FLOATS * 4)

__global__ __launch_bounds__(256, 1) void conv_mma_kernel(
    const float* __restrict__ Acl, const float* __restrict__ Wt,
    const float* __restrict__ bias, float* __restrict__ out,
    int flags, const float* __restrict__ r1, const float* __restrict__ r2)
{
    extern __shared__ float sm[];
    float* sA = sm;
    float* sW = sm + SW_OFF;
    const int tid = threadIdx.x;
    const int lane = tid & 31;
    const int g = lane >> 2;
    const int tig = lane & 3;
    const int wid = tid >> 5;
    const int mbase = (wid & 1) * 64;
    const int nbase = (wid >> 1) * 48;
    const int t = blockIdx.x;
    const float* Arow = Acl + (size_t)t * TILE_ELEMS;

    float c[4][6][4];
#pragma unroll
    for (int mt = 0; mt < 4; mt++)
#pragma unroll
        for (int nt = 0; nt < 6; nt++)
#pragma unroll
            for (int r = 0; r < 4; r++) c[mt][nt][r] = 0.f;

    for (int kc = 0; kc < 6; kc++) {
#pragma unroll
        for (int r = 0; r < 4; r++) {
            int f = tid + 256 * r;
            int pix = f >> 3, c4 = f & 7;
            float4 v = *(const float4*)(Arow + (size_t)pix * C_ + kc * 32 + c4 * 4);
            *(float4*)&sA[pix * SAS + c4 * 4] = v;
        }
#pragma unroll
        for (int r = 0; r < 6; r++) {
            int f = tid + 256 * r;
            int o = f >> 3, c4 = f & 7;
            float4 v = to_tf32_4(*(const float4*)(Wt + (size_t)o * C_ + kc * 32 + c4 * 4));
            *(float4*)&sW[o * SAS + c4 * 4] = v;
        }
        __syncthreads();
#pragma unroll
        for (int kk = 0; kk < 4; kk++) {
            const int k0 = kk * 8 + tig;
            uint32_t a[4][4], b[6][2];
#pragma unroll
            for (int mt = 0; mt < 4; mt++) {
                int row = mbase + mt * 16 + g;
                a[mt][0] = __float_as_uint(sA[row * SAS + k0]);
                a[mt][1] = __float_as_uint(sA[(row + 8) * SAS + k0]);
                a[mt][2] = __float_as_uint(sA[row * SAS + k0 + 4]);
                a[mt][3] = __float_as_uint(sA[(row + 8) * SAS + k0 + 4]);
            }
#pragma unroll
            for (int nt = 0; nt < 6; nt++) {
                int col = nbase + nt * 8 + g;
                b[nt][0] = __float_as_uint(sW[col * SAS + k0]);
                b[nt][1] = __float_as_uint(sW[col * SAS + k0 + 4]);
            }
#pragma unroll
            for (int mt = 0; mt < 4; mt++)
#pragma unroll
                for (int nt = 0; nt < 6; nt++)
                    mma_tf32(c[mt][nt], a[mt], b[nt]);
        }
        __syncthreads();
    }

    const int gelu = flags & 1;
    float bv[6][2];
#pragma unroll
    for (int nt = 0; nt < 6; nt++) {
        int o = nbase + nt * 8 + 2 * tig;
        bv[nt][0] = __ldg(&bias[o]);
        bv[nt][1] = __ldg(&bias[o + 1]);
    }

    if (flags & 2) {
        float* sO = sm;
#pragma unroll
        for (int mt = 0; mt < 4; mt++) {
            int row0 = mbase + mt * 16 + g;
#pragma unroll
            for (int nt = 0; nt < 6; nt++) {
                int o = nbase + nt * 8 + 2 * tig;
#pragma unroll
                for (int half = 0; half < 2; half++) {
                    int row = row0 + half * 8;
                    float v0 = c[mt][nt][half * 2 + 0] + bv[nt][0];
                    float v1 = c[mt][nt][half * 2 + 1] + bv[nt][1];
                    if (gelu) {
                        v0 = 0.5f * v0 * (1.0f + erff(v0 * 0.70710678118654752f));
                        v1 = 0.5f * v1 * (1.0f + erff(v1 * 0.70710678118654752f));
                    }
                    float2 w = {to_tf32(v0), to_tf32(v1)};
                    *(float2*)&sO[row * 196 + o] = w;
                }
            }
        }
        __syncthreads();
        float* ob = out + (size_t)t * TILE_ELEMS;
#pragma unroll
        for (int r = 0; r < 24; r++) {
            int f = tid + 256 * r;
            int pix = f / 48, c4 = f % 48;
            *(float4*)(ob + (size_t)pix * C_ + c4 * 4) = *(float4*)&sO[pix * 196 + c4 * 4];
        }
    } else {
        const int pg0 = t << 7;
        const int b = pg0 >> 14;
        const int p0 = pg0 & (HW_ - 1);
#pragma unroll
        for (int mt = 0; mt < 4; mt++) {
            int row0 = mbase + mt * 16 + g;
#pragma unroll
            for (int nt = 0; nt < 6; nt++) {
                int o = nbase + nt * 8 + 2 * tig;
#pragma unroll
                for (int half = 0; half < 2; half++) {
                    int row = row0 + half * 8;
#pragma unroll
                    for (int cc = 0; cc < 2; cc++) {
                        float v = c[mt][nt][half * 2 + cc] + bv[nt][cc];
                        if (gelu) v = 0.5f * v * (1.0f + erff(v * 0.70710678118654752f));
                        size_t idx = ((size_t)(b * C_ + o + cc) << 14) + p0 + row;
                        if (r1) v += __ldg(&r1[idx]) + __ldg(&r2[idx]);
                        out[idx] = v;
                    }
                }
            }
        }
    }
}

// ---------------- norms (unchanged) ----------------
__global__ __launch_bounds__(256) void norm_kernel(
    const float* __restrict__ o1, const float* __restrict__ o2,
    float* __restrict__ n1h, float* __restrict__ n1w,
    float* __restrict__ n2h, float* __restrict__ n2w)
{
    const int bh = blockIdx.x;
    const int src = blockIdx.y;
    const int tid = threadIdx.x;
    const float* base = (src ? o2 : o1) + ((size_t)(bh >> 3) * C_ + (bh & 7) * CPH_) * HW_;

    __shared__ float sRow[128];
    __shared__ float sColA[256];
    if (tid < 128) sRow[tid] = 0.f;
    __syncthreads();

    float colAcc = 0.f;
    for (int idx = tid; idx < CPH_ * HW_; idx += 256) {
        float v = base[idx];
        v *= v;
        colAcc += v;
        float rv = v;
#pragma unroll
        for (int s = 16; s >= 1; s >>= 1) rv += __shfl_xor_sync(0xffffffffu, rv, s);
        if ((tid & 31) == 0) atomicAdd(&sRow[(idx >> 7) & 127], rv);
    }
    sColA[tid] = colAcc;
    __syncthreads();
    if (tid < 128) {
        float cs = sColA[tid] + sColA[tid + 128];
        float rs = sRow[tid];
        if (src) { n2h[bh * 128 + tid] = sqrtf(rs); n2w[bh * 128 + tid] = sqrtf(cs); }
        else     { n1h[bh * 128 + tid] = sqrtf(rs); n1w[bh * 128 + tid] = sqrtf(cs); }
    }
}

// ---------------- attention via tf32 mma + fused softmax ----------------
// grid (64 bh, 2 mode), 256 thr. Out 128x128, K = 3072 in 96 chunks of 32.
// mode0: A rows = o2[y][x-chunk], B rows = o1. mode1: A rows = o1t[x][y-chunk], B = o2t.
#define ATTN_SMEM_BYTES (128 * 132 * 4)   // logits; staging (2*128*36*4=36864) fits inside

__global__ __launch_bounds__(256, 1) void attn_mma_kernel(
    const float* __restrict__ o1, const float* __restrict__ o2,
    const float* __restrict__ o1t, const float* __restrict__ o2t,
    const float* __restrict__ n1h, const float* __restrict__ n2h,
    const float* __restrict__ n1w, const float* __restrict__ n2w,
    const float* __restrict__ pbh, const float* __restrict__ pbw,
    float* __restrict__ attn1, float* __restrict__ attn2)
{
    extern __shared__ float sm[];
    float* sA = sm;              // [128][36]
    float* sB = sm + 128 * SAS;  // [128][36]
    const int bh = blockIdx.x;
    const int mode = blockIdx.y;
    const int hd = bh & 7, b = bh >> 3;
    const int tid = threadIdx.x;
    const int lane = tid & 31, g = lane >> 2, tig = lane & 3;
    const int wid = tid >> 5;
    const int mbase = (wid & 1) * 64;
    const int nbase = (wid >> 1) * 32;
    const float* Abase = (mode ? o1t : o2) + ((size_t)b * C_ + hd * CPH_) * HW_;
    const float* Bbase = (mode ? o2t : o1) + ((size_t)b * C_ + hd * CPH_) * HW_;

    float acc[4][4][4];
#pragma unroll
    for (int mt = 0; mt < 4; mt++)
#pragma unroll
        for (int nt = 0; nt < 4; nt++)
#pragma unroll
            for (int e = 0; e < 4; e++) acc[mt][nt][e] = 0.f;

    const int prow = tid >> 3, pc4 = tid & 7;   // this thread's f4 slot (+256*r)
    float4 pa[4], pb[4];
#pragma unroll
    for (int r = 0; r < 4; r++) {
        int row = prow + 32 * r;
        pa[r] = *(const float4*)(Abase + row * 128 + pc4 * 4);
        pb[r] = *(const float4*)(Bbase + row * 128 + pc4 * 4);
    }

    for (int kc = 0; kc < 96; kc++) {
#pragma unroll
        for (int r = 0; r < 4; r++) {
            int row = prow + 32 * r;
            *(float4*)&sA[row * SAS + pc4 * 4] = to_tf32_4(pa[r]);
            *(float4*)&sB[row * SAS + pc4 * 4] = to_tf32_4(pb[r]);
        }
        __syncthreads();
        if (kc < 95) {
            int off = ((kc + 1) >> 2) * HW_ + ((kc + 1) & 3) * 32;
#pragma unroll
            for (int r = 0; r < 4; r++) {
                int row = prow + 32 * r;
                pa[r] = *(const float4*)(Abase + off + row * 128 + pc4 * 4);
                pb[r] = *(const float4*)(Bbase + off + row * 128 + pc4 * 4);
            }
        }
#pragma unroll
        for (int k4 = 0; k4 < 4; k4++) {
            const int k0 = k4 * 8 + tig;
            uint32_t a[4][4], bf[4][2];
#pragma unroll
            for (int mt = 0; mt < 4; mt++) {
                int row = mbase + mt * 16 + g;
                a[mt][0] = __float_as_uint(sA[row * SAS + k0]);
                a[mt][1] = __float_as_uint(sA[(row + 8) * SAS + k0]);
                a[mt][2] = __float_as_uint(sA[row * SAS + k0 + 4]);
                a[mt][3] = __float_as_uint(sA[(row + 8) * SAS + k0 + 4]);
            }
#pragma unroll
            for (int nt = 0; nt < 4; nt++) {
                int col = nbase + nt * 8 + g;
                bf[nt][0] = __float_as_uint(sB[col * SAS + k0]);
                bf[nt][1] = __float_as_uint(sB[col * SAS + k0 + 4]);
            }
#pragma unroll
            for (int mt = 0; mt < 4; mt++)
#pragma unroll
                for (int nt = 0; nt < 4; nt++)
                    mma_tf32(acc[mt][nt], a[mt], bf[nt]);
        }
        __syncthreads();
    }

    // scale + bias -> smem logits
    const float* nI = mode ? n1w : n2h;
    const float* nJ = mode ? n2w : n1h;
    const float bias = mode ? __ldg(&pbw[hd]) : __ldg(&pbh[hd]);
    float rinv[8], cinv[8];
#pragma unroll
    for (int mt = 0; mt < 4; mt++)
#pragma unroll
        for (int half = 0; half < 2; half++) {
            int row = mbase + mt * 16 + g + half * 8;
            rinv[mt * 2 + half] = TEMP_INV / fmaxf(__ldg(&nI[bh * 128 + row]), EPS_);
        }
#pragma unroll
    for (int nt = 0; nt < 4; nt++)
#pragma unroll
        for (int cc = 0; cc < 2; cc++) {
            int col = nbase + nt * 8 + 2 * tig + cc;
            cinv[nt * 2 + cc] = 1.f / fmaxf(__ldg(&nJ[bh * 128 + col]), EPS_);
        }
    float* sc = sm;   // [128][132]
#pragma unroll
    for (int mt = 0; mt < 4; mt++)
#pragma unroll
        for (int half = 0; half < 2; half++) {
            int row = mbase + mt * 16 + g + half * 8;
            float ri = rinv[mt * 2 + half];
#pragma unroll
            for (int nt = 0; nt < 4; nt++) {
                int col = nbase + nt * 8 + 2 * tig;
                float2 v;
                v.x = acc[mt][nt][half * 2 + 0] * (ri * cinv[nt * 2 + 0]) + bias;
                v.y = acc[mt][nt][half * 2 + 1] * (ri * cinv[nt * 2 + 1]) + bias;
                *(float2*)&sc[row * 132 + col] = v;
            }
        }
    __syncthreads();

    // softmax: warp per row (16 rows per warp), float4 per lane
    float* outp = (mode ? attn2 : attn1) + (size_t)bh * HW_;
    for (int r = wid; r < 128; r += 8) {
        float4 v = *(float4*)&sc[r * 132 + lane * 4];
        float m = fmaxf(fmaxf(v.x, v.y), fmaxf(v.z, v.w));
#pragma unroll
        for (int s = 16; s >= 1; s >>= 1) m = fmaxf(m, __shfl_xor_sync(0xffffffffu, m, s));
        v.x = __expf(v.x - m); v.y = __expf(v.y - m);
        v.z = __expf(v.z - m); v.w = __expf(v.w - m);
        float su = v.x + v.y + v.z + v.w;
#pragma unroll
        for (int s = 16; s >= 1; s >>= 1) su += __shfl_xor_sync(0xffffffffu, su, s);
        float inv = 1.f / su;
        v.x *= inv; v.y *= inv; v.z *= inv; v.w *= inv;
        *(float4*)&outp[r * 128 + lane * 4] = v;
    }
}

// ---------------- AV + q-residual + gated fusion via tf32 mma ----------------
// grid (192, 8). Per block: two 128x128x128 GEMMs (sequential passes), fused epilogue.
#define AVS 132
#define AV_SMEM_BYTES (2 * 128 * AVS * 4)   // 135168

__global__ __launch_bounds__(256, 1) void av_mma_kernel(
    const float* __restrict__ o1, const float* __restrict__ o2,
    const float* __restrict__ o1t,
    const float* __restrict__ attn1, const float* __restrict__ attn2,
    const float* __restrict__ n2h, const float* __restrict__ n1w,
    const float* __restrict__ gate, float* __restrict__ fus)
{
    extern __shared__ float sm[];
    float* sA = sm;                 // [128][132]
    float* sB = sm + 128 * AVS;     // [128][132]
    const int ch = blockIdx.x, b = blockIdx.y;
    const int hd = ch / CPH_;
    const int bh = b * 8 + hd;
    const int tid = threadIdx.x;
    const int lane = tid & 31, g = lane >> 2, tig = lane & 3;
    const int wid = tid >> 5;
    const int mbase = (wid & 1) * 64;
    const int nbase = (wid >> 1) * 32;

    const float* A1 = attn1 + (size_t)bh * HW_;
    const float* Bs1 = o1t + ((size_t)b * C_ + ch) * HW_;   // [x][y]
    const float* A2 = o2 + ((size_t)b * C_ + ch) * HW_;     // [y][x]
    const float* B2 = attn2 + (size_t)bh * HW_;
    const float* S1 = o1 + ((size_t)b * C_ + ch) * HW_;
    const float* S2 = A2;

    float acc1[4][4][4], acc2[4][4][4];
#pragma unroll
    for (int mt = 0; mt < 4; mt++)
#pragma unroll
        for (int nt = 0; nt < 4; nt++)
#pragma unroll
            for (int e = 0; e < 4; e++) { acc1[mt][nt][e] = 0.f; acc2[mt][nt][e] = 0.f; }

    const int prow = tid >> 3, pc4 = tid & 7;

#pragma unroll 1
    for (int pass = 0; pass < 2; pass++) {
        const float* Ap = pass ? A2 : A1;
        const float* Bp = pass ? B2 : Bs1;
        if (pass) __syncthreads();
#pragma unroll
        for (int r = 0; r < 4; r++) {
            int row = prow + 32 * r;
#pragma unroll
            for (int q = 0; q < 4; q++) {
                float4 va = to_tf32_4(*(const float4*)(Ap + row * 128 + (pc4 + 8 * q) * 4));
                float4 vb = to_tf32_4(*(const float4*)(Bp + row * 128 + (pc4 + 8 * q) * 4));
                *(float4*)&sA[row * AVS + (pc4 + 8 * q) * 4] = va;
                *(float4*)&sB[row * AVS + (pc4 + 8 * q) * 4] = vb;
            }
        }
        __syncthreads();
        float (*acc)[4][4] = pass ? acc2 : acc1;
#pragma unroll
        for (int k4 = 0; k4 < 16; k4++) {
            const int k0 = k4 * 8 + tig;
            uint32_t a[4][4], bf[4][2];
#pragma unroll
            for (int mt = 0; mt < 4; mt++) {
                int row = mbase + mt * 16 + g;
                a[mt][0] = __float_as_uint(sA[row * AVS + k0]);
                a[mt][1] = __float_as_uint(sA[(row + 8) * AVS + k0]);
                a[mt][2] = __float_as_uint(sA[row * AVS + k0 + 4]);
                a[mt][3] = __float_as_uint(sA[(row + 8) * AVS + k0 + 4]);
            }
#pragma unroll
            for (int nt = 0; nt < 4; nt++) {
                int col = nbase + nt * 8 + g;
                bf[nt][0] = __float_as_uint(sB[col * AVS + k0]);
                bf[nt][1] = __float_as_uint(sB[col * AVS + k0 + 4]);
            }
#pragma unroll
            for (int mt = 0; mt < 4; mt++)
#pragma unroll
                for (int nt = 0; nt < 4; nt++)
                    mma_tf32(acc[mt][nt], a[mt], bf[nt]);
        }
    }

    const float gg = 1.f / (1.f + expf(-__ldg(&gate[0])));
    float invy[8], invx[8];
#pragma unroll
    for (int mt = 0; mt < 4; mt++)
#pragma unroll
        for (int half = 0; half < 2; half++) {
            int row = mbase + mt * 16 + g + half * 8;
            invy[mt * 2 + half] = 1.f / fmaxf(__ldg(&n2h[bh * 128 + row]), EPS_);
        }
#pragma unroll
    for (int nt = 0; nt < 4; nt++)
#pragma unroll
        for (int cc = 0; cc < 2; cc++) {
            int col = nbase + nt * 8 + 2 * tig + cc;
            invx[nt * 2 + cc] = 1.f / fmaxf(__ldg(&n1w[bh * 128 + col]), EPS_);
        }

    float* fout = fus + ((size_t)b * C_ + ch) * HW_;
#pragma unroll
    for (int mt = 0; mt < 4; mt++)
#pragma unroll
        for (int half = 0; half < 2; half++) {
            int row = mbase + mt * 16 + g + half * 8;
            float iy = invy[mt * 2 + half];
#pragma unroll
            for (int nt = 0; nt < 4; nt++) {
                int col = nbase + nt * 8 + 2 * tig;
                float2 s1v = *(const float2*)(S1 + row * 128 + col);
                float2 s2v = *(const float2*)(S2 + row * 128 + col);
                float2 o;
                o.x = gg * (acc1[mt][nt][half * 2 + 0] + s2v.x * iy)
                    + (1.f - gg) * (acc2[mt][nt][half * 2 + 0] + s1v.x * invx[nt * 2 + 0]);
                o.y = gg * (acc1[mt][nt][half * 2 + 1] + s2v.y * iy)
                    + (1.f - gg) * (acc2[mt][nt][half * 2 + 1] + s1v.y * invx[nt * 2 + 1]);
                *(float2*)(fout + row * 128 + col) = o;
            }
        }
}

// ---------------- host launcher ----------------
extern "C" void kernel_launch(void* const* d_in, const int* in_sizes, int n_in,
                              void* d_out, int out_size)
{
    const float* x1  = (const float*)d_in[0];
    const float* x2  = (const float*)d_in[1];
    const float* Wp  = (const float*)d_in[2];
    const float* bp  = (const float*)d_in[3];
    const float* gate= (const float*)d_in[4];
    const float* pbh = (const float*)d_in[5];
    const float* pbw = (const float*)d_in[6];
    const float* Wm1 = (const float*)d_in[7];
    const float* bm1 = (const float*)d_in[8];
    const float* Wm2 = (const float*)d_in[9];
    const float* bm2 = (const float*)d_in[10];
    float* out = (float*)d_out;

    float *p_o1, *p_o2, *p_o1t, *p_o2t, *p_fus, *p_cl, *p_a1, *p_a2;
    float *p_n1h, *p_n2h, *p_n1w, *p_n2w;
    cudaGetSymbolAddress((void**)&p_o1, g_o1);
    cudaGetSymbolAddress((void**)&p_o2, g_o2);
    cudaGetSymbolAddress((void**)&p_o1t, g_o1t);
    cudaGetSymbolAddress((void**)&p_o2t, g_o2t);
    cudaGetSymbolAddress((void**)&p_fus, g_fus);
    cudaGetSymbolAddress((void**)&p_cl, g_cl);
    cudaGetSymbolAddress((void**)&p_a1, g_attn1);
    cudaGetSymbolAddress((void**)&p_a2, g_attn2);
    cudaGetSymbolAddress((void**)&p_n1h, g_n1h);
    cudaGetSymbolAddress((void**)&p_n2h, g_n2h);
    cudaGetSymbolAddress((void**)&p_n1w, g_n1w);
    cudaGetSymbolAddress((void**)&p_n2w, g_n2w);

    cudaFuncSetAttribute(conv_mma_kernel, cudaFuncAttributeMaxDynamicSharedMemorySize, SMEM_BYTES);
    cudaFuncSetAttribute(attn_mma_kernel, cudaFuncAttributeMaxDynamicSharedMemorySize, ATTN_SMEM_BYTES);
    cudaFuncSetAttribute(av_mma_kernel, cudaFuncAttributeMaxDynamicSharedMemorySize, AV_SMEM_BYTES);

    dim3 tGrid(HW_ / 32, C_ / 32, B_);
    dim3 tBlk(32, 8);
    dim3 rGrid(16, C_, B_);

    transpose_cf_cl_kernel<<<tGrid, tBlk>>>(x1, p_cl);
    conv_mma_kernel<<<NTILES_, 256, SMEM_BYTES>>>(p_cl, Wp, bp, p_o1, 0, nullptr, nullptr);
    transpose_cf_cl_kernel<<<tGrid, tBlk>>>(x2, p_cl);
    conv_mma_kernel<<<NTILES_, 256, SMEM_BYTES>>>(p_cl, Wp, bp, p_o2, 0, nullptr, nullptr);

    norm_kernel<<<dim3(B_ * HEADS_, 2), 256>>>(p_o1, p_o2, p_n1h, p_n1w, p_n2h, p_n2w);
    repack_kernel<<<rGrid, tBlk>>>(p_o1, p_o1t);
    repack_kernel<<<rGrid, tBlk>>>(p_o2, p_o2t);

    attn_mma_kernel<<<dim3(B_ * HEADS_, 2), 256, ATTN_SMEM_BYTES>>>(
        p_o1, p_o2, p_o1t, p_o2t, p_n1h, p_n2h, p_n1w, p_n2w, pbh, pbw, p_a1, p_a2);

    av_mma_kernel<<<dim3(C_, B_), 256, AV_SMEM_BYTES>>>(
        p_o1, p_o2, p_o1t, p_a1, p_a2, p_n2h, p_n1w, gate, p_fus);

    transpose_cf_cl_kernel<<<tGrid, tBlk>>>(p_fus, p_cl);
    conv_mma_kernel<<<NTILES_, 256, SMEM_BYTES>>>(p_cl, Wp, bp, p_o1, 2, nullptr, nullptr);
    conv_mma_kernel<<<NTILES_, 256, SMEM_BYTES>>>(p_o1, Wm1, bm1, p_o2, 3, nullptr, nullptr);
    conv_mma_kernel<<<NTILES_, 256, SMEM_BYTES>>>(p_o2, Wm2, bm2, out, 0, x1, x2);

    (void)in_sizes; (void)n_in; (void)out_size;
}

// round 5
// speedup vs baseline: 1.6434x; 1.0935x over previous
#include <cuda_runtime.h>
#include <math.h>
#include <stdint.h>

#define B_ 8
#define C_ 192
#define H_ 128
#define W_ 128
#define HW_ 16384
#define HEADS_ 8
#define CPH_ 24
#define TEMP_INV 100.0f
#define EPS_ 1e-12f

#define NPIX_ (B_ * HW_)
#define NTILES_ (NPIX_ / 128)
#define TILE_ELEMS (128 * C_)

// ---------------- scratch ----------------
__device__ float g_o1[(size_t)B_ * C_ * HW_];
__device__ float g_o2[(size_t)B_ * C_ * HW_];
__device__ float g_o1t[(size_t)B_ * C_ * HW_];
__device__ float g_o2t[(size_t)B_ * C_ * HW_];
__device__ float g_fus[(size_t)B_ * C_ * HW_];
__device__ float g_cl[(size_t)NPIX_ * C_];
__device__ float g_attn1[(size_t)B_ * HEADS_ * HW_];
__device__ float g_attn2[(size_t)B_ * HEADS_ * HW_];
__device__ float g_n1h[B_ * HEADS_ * H_];
__device__ float g_n2h[B_ * HEADS_ * H_];
__device__ float g_n1w[B_ * HEADS_ * W_];
__device__ float g_n2w[B_ * HEADS_ * W_];

__device__ __forceinline__ float to_tf32(float x) {
    uint32_t u; asm("cvt.rna.tf32.f32 %0, %1;" : "=r"(u) : "f"(x));
    return __uint_as_float(u);
}
__device__ __forceinline__ float4 to_tf32_4(float4 v) {
    v.x = to_tf32(v.x); v.y = to_tf32(v.y); v.z = to_tf32(v.z); v.w = to_tf32(v.w);
    return v;
}

__device__ __forceinline__ void mma_tf32(float* c, const uint32_t* a, const uint32_t* b) {
    asm volatile(
        "mma.sync.aligned.m16n8k8.row.col.f32.tf32.tf32.f32 "
        "{%0,%1,%2,%3}, {%4,%5,%6,%7}, {%8,%9}, {%0,%1,%2,%3};"
        : "+f"(c[0]), "+f"(c[1]), "+f"(c[2]), "+f"(c[3])
        : "r"(a[0]), "r"(a[1]), "r"(a[2]), "r"(a[3]), "r"(b[0]), "r"(b[1]));
}

// ---------------- transpose: channel-first -> channel-last, tf32-rounded ----
__global__ __launch_bounds__(256) void transpose_cf_cl_kernel(
    const float* __restrict__ in, float* __restrict__ out)
{
    __shared__ float t[32][33];
    const int b = blockIdx.z;
    const int p0 = blockIdx.x * 32;
    const int c0 = blockIdx.y * 32;
    const int tx = threadIdx.x, ty = threadIdx.y;
    const float* ib = in + (size_t)b * C_ * HW_;
    float* ob = out + (size_t)b * HW_ * C_;
#pragma unroll
    for (int i = ty; i < 32; i += 8)
        t[i][tx] = ib[(size_t)(c0 + i) * HW_ + p0 + tx];
    __syncthreads();
#pragma unroll
    for (int i = ty; i < 32; i += 8)
        ob[(size_t)(p0 + i) * C_ + c0 + tx] = to_tf32(t[tx][i]);
}

// ---------------- repack: per (b,c) [y][x] -> [x][y] ----------------
__global__ __launch_bounds__(256) void repack_kernel(
    const float* __restrict__ in, float* __restrict__ out)
{
    __shared__ float t[32][33];
    const int c = blockIdx.y, b = blockIdx.z;
    const int x0 = (blockIdx.x & 3) * 32, y0 = (blockIdx.x >> 2) * 32;
    const int tx = threadIdx.x, ty = threadIdx.y;
    const float* ib = in + ((size_t)b * C_ + c) * HW_;
    float* ob = out + ((size_t)b * C_ + c) * HW_;
#pragma unroll
    for (int i = ty; i < 32; i += 8)
        t[i][tx] = ib[(y0 + i) * 128 + x0 + tx];
    __syncthreads();
#pragma unroll
    for (int i = ty; i < 32; i += 8)
        ob[(x0 + i) * 128 + y0 + tx] = t[tx][i];
}

// ---------------- conv1x1 via mma.sync tf32, double-buffered ----------------
#define SAS 36
#define CONV_ABUF (128 * SAS)              // 4608 floats per A buffer
#define CONV_WBUF (192 * SAS)              // 6912 floats per W buffer
#define CONV_SMEM_FLOATS (128 * 196)       // epilogue staging = 25088 > 2*(4608+6912)=23040
#define SMEM_BYTES (CONV_SMEM_FLOATS * 4)  // 100352

__global__ __launch_bounds__(256, 1) void conv_mma_kernel(
    const float* __restrict__ Acl, const float* __restrict__ Wt,
    const float* __restrict__ bias, float* __restrict__ out,
    int flags, const float* __restrict__ r1, const float* __restrict__ r2)
{
    extern __shared__ float sm[];
    const int tid = threadIdx.x;
    const int lane = tid & 31;
    const int g = lane >> 2;
    const int tig = lane & 3;
    const int wid = tid >> 5;
    const int mbase = (wid & 1) * 64;
    const int nbase = (wid >> 1) * 48;
    const int t = blockIdx.x;
    const float* Arow = Acl + (size_t)t * TILE_ELEMS;

    float c[4][6][4];
#pragma unroll
    for (int mt = 0; mt < 4; mt++)
#pragma unroll
        for (int nt = 0; nt < 6; nt++)
#pragma unroll
            for (int r = 0; r < 4; r++) c[mt][nt][r] = 0.f;

    // per-thread staging slots
    const int apix = tid >> 3, ac4 = tid & 7;        // A: rows tid/8 (+32*r)... use f pattern
    float4 pa[4], pw[6];
    // prefetch chunk 0
#pragma unroll
    for (int r = 0; r < 4; r++) {
        int f = tid + 256 * r;
        int pix = f >> 3, c4 = f & 7;
        pa[r] = *(const float4*)(Arow + (size_t)pix * C_ + c4 * 4);
    }
#pragma unroll
    for (int r = 0; r < 6; r++) {
        int f = tid + 256 * r;
        int o = f >> 3, c4 = f & 7;
        pw[r] = *(const float4*)(Wt + (size_t)o * C_ + c4 * 4);
    }

    for (int kc = 0; kc < 6; kc++) {
        float* dA = sm + (kc & 1) * CONV_ABUF;
        float* dW = sm + 2 * CONV_ABUF + (kc & 1) * CONV_WBUF;
#pragma unroll
        for (int r = 0; r < 4; r++) {
            int f = tid + 256 * r;
            int pix = f >> 3, c4 = f & 7;
            *(float4*)&dA[pix * SAS + c4 * 4] = pa[r];
        }
#pragma unroll
        for (int r = 0; r < 6; r++) {
            int f = tid + 256 * r;
            int o = f >> 3, c4 = f & 7;
            *(float4*)&dW[o * SAS + c4 * 4] = to_tf32_4(pw[r]);
        }
        __syncthreads();
        if (kc < 5) {
            int ko = (kc + 1) * 32;
#pragma unroll
            for (int r = 0; r < 4; r++) {
                int f = tid + 256 * r;
                int pix = f >> 3, c4 = f & 7;
                pa[r] = *(const float4*)(Arow + (size_t)pix * C_ + ko + c4 * 4);
            }
#pragma unroll
            for (int r = 0; r < 6; r++) {
                int f = tid + 256 * r;
                int o = f >> 3, c4 = f & 7;
                pw[r] = *(const float4*)(Wt + (size_t)o * C_ + ko + c4 * 4);
            }
        }
#pragma unroll
        for (int kk = 0; kk < 4; kk++) {
            const int k0 = kk * 8 + tig;
            uint32_t a[4][4], b[6][2];
#pragma unroll
            for (int mt = 0; mt < 4; mt++) {
                int row = mbase + mt * 16 + g;
                a[mt][0] = __float_as_uint(dA[row * SAS + k0]);
                a[mt][1] = __float_as_uint(dA[(row + 8) * SAS + k0]);
                a[mt][2] = __float_as_uint(dA[row * SAS + k0 + 4]);
                a[mt][3] = __float_as_uint(dA[(row + 8) * SAS + k0 + 4]);
            }
#pragma unroll
            for (int nt = 0; nt < 6; nt++) {
                int col = nbase + nt * 8 + g;
                b[nt][0] = __float_as_uint(dW[col * SAS + k0]);
                b[nt][1] = __float_as_uint(dW[col * SAS + k0 + 4]);
            }
#pragma unroll
            for (int mt = 0; mt < 4; mt++)
#pragma unroll
                for (int nt = 0; nt < 6; nt++)
                    mma_tf32(c[mt][nt], a[mt], b[nt]);
        }
    }
    __syncthreads();

    const int gelu = flags & 1;
    float bv[6][2];
#pragma unroll
    for (int nt = 0; nt < 6; nt++) {
        int o = nbase + nt * 8 + 2 * tig;
        bv[nt][0] = __ldg(&bias[o]);
        bv[nt][1] = __ldg(&bias[o + 1]);
    }

    if (flags & 2) {
        float* sO = sm;
#pragma unroll
        for (int mt = 0; mt < 4; mt++) {
            int row0 = mbase + mt * 16 + g;
#pragma unroll
            for (int nt = 0; nt < 6; nt++) {
                int o = nbase + nt * 8 + 2 * tig;
#pragma unroll
                for (int half = 0; half < 2; half++) {
                    int row = row0 + half * 8;
                    float v0 = c[mt][nt][half * 2 + 0] + bv[nt][0];
                    float v1 = c[mt][nt][half * 2 + 1] + bv[nt][1];
                    if (gelu) {
                        v0 = 0.5f * v0 * (1.0f + erff(v0 * 0.70710678118654752f));
                        v1 = 0.5f * v1 * (1.0f + erff(v1 * 0.70710678118654752f));
                    }
                    float2 w = {to_tf32(v0), to_tf32(v1)};
                    *(float2*)&sO[row * 196 + o] = w;
                }
            }
        }
        __syncthreads();
        float* ob = out + (size_t)t * TILE_ELEMS;
#pragma unroll
        for (int r = 0; r < 24; r++) {
            int f = tid + 256 * r;
            int pix = f / 48, c4 = f % 48;
            *(float4*)(ob + (size_t)pix * C_ + c4 * 4) = *(float4*)&sO[pix * 196 + c4 * 4];
        }
    } else {
        const int pg0 = t << 7;
        const int b = pg0 >> 14;
        const int p0 = pg0 & (HW_ - 1);
#pragma unroll
        for (int mt = 0; mt < 4; mt++) {
            int row0 = mbase + mt * 16 + g;
#pragma unroll
            for (int nt = 0; nt < 6; nt++) {
                int o = nbase + nt * 8 + 2 * tig;
#pragma unroll
                for (int half = 0; half < 2; half++) {
                    int row = row0 + half * 8;
#pragma unroll
                    for (int cc = 0; cc < 2; cc++) {
                        float v = c[mt][nt][half * 2 + cc] + bv[nt][cc];
                        if (gelu) v = 0.5f * v * (1.0f + erff(v * 0.70710678118654752f));
                        size_t idx = ((size_t)(b * C_ + o + cc) << 14) + p0 + row;
                        if (r1) v += __ldg(&r1[idx]) + __ldg(&r2[idx]);
                        out[idx] = v;
                    }
                }
            }
        }
    }
    (void)apix; (void)ac4;
}

// ---------------- norms ----------------
__global__ __launch_bounds__(256) void norm_kernel(
    const float* __restrict__ o1, const float* __restrict__ o2,
    float* __restrict__ n1h, float* __restrict__ n1w,
    float* __restrict__ n2h, float* __restrict__ n2w)
{
    const int bh = blockIdx.x;
    const int src = blockIdx.y;
    const int tid = threadIdx.x;
    const float* base = (src ? o2 : o1) + ((size_t)(bh >> 3) * C_ + (bh & 7) * CPH_) * HW_;

    __shared__ float sRow[128];
    __shared__ float sColA[256];
    if (tid < 128) sRow[tid] = 0.f;
    __syncthreads();

    float colAcc = 0.f;
    for (int idx = tid; idx < CPH_ * HW_; idx += 256) {
        float v = base[idx];
        v *= v;
        colAcc += v;
        float rv = v;
#pragma unroll
        for (int s = 16; s >= 1; s >>= 1) rv += __shfl_xor_sync(0xffffffffu, rv, s);
        if ((tid & 31) == 0) atomicAdd(&sRow[(idx >> 7) & 127], rv);
    }
    sColA[tid] = colAcc;
    __syncthreads();
    if (tid < 128) {
        float cs = sColA[tid] + sColA[tid + 128];
        float rs = sRow[tid];
        if (src) { n2h[bh * 128 + tid] = sqrtf(rs); n2w[bh * 128 + tid] = sqrtf(cs); }
        else     { n1h[bh * 128 + tid] = sqrtf(rs); n1w[bh * 128 + tid] = sqrtf(cs); }
    }
}

// ---------------- attention via tf32 mma, double-buffered, fused softmax ----------------
#define ATTN_ABUF (128 * SAS)                   // 4608 floats
#define ATTN_SMEM_FLOATS (4 * ATTN_ABUF)        // 18432 floats (> logits 128*132=16896)
#define ATTN_SMEM_BYTES (ATTN_SMEM_FLOATS * 4)  // 73728

__global__ __launch_bounds__(256, 1) void attn_mma_kernel(
    const float* __restrict__ o1, const float* __restrict__ o2,
    const float* __restrict__ o1t, const float* __restrict__ o2t,
    const float* __restrict__ n1h, const float* __restrict__ n2h,
    const float* __restrict__ n1w, const float* __restrict__ n2w,
    const float* __restrict__ pbh, const float* __restrict__ pbw,
    float* __restrict__ attn1, float* __restrict__ attn2)
{
    extern __shared__ float sm[];
    const int bh = blockIdx.x;
    const int mode = blockIdx.y;
    const int hd = bh & 7, b = bh >> 3;
    const int tid = threadIdx.x;
    const int lane = tid & 31, g = lane >> 2, tig = lane & 3;
    const int wid = tid >> 5;
    const int mbase = (wid & 1) * 64;
    const int nbase = (wid >> 1) * 32;
    const float* Abase = (mode ? o1t : o2) + ((size_t)b * C_ + hd * CPH_) * HW_;
    const float* Bbase = (mode ? o2t : o1) + ((size_t)b * C_ + hd * CPH_) * HW_;

    float acc[4][4][4];
#pragma unroll
    for (int mt = 0; mt < 4; mt++)
#pragma unroll
        for (int nt = 0; nt < 4; nt++)
#pragma unroll
            for (int e = 0; e < 4; e++) acc[mt][nt][e] = 0.f;

    const int prow = tid >> 3, pc4 = tid & 7;
    float4 pa[4], pb[4];
#pragma unroll
    for (int r = 0; r < 4; r++) {
        int row = prow + 32 * r;
        pa[r] = *(const float4*)(Abase + row * 128 + pc4 * 4);
        pb[r] = *(const float4*)(Bbase + row * 128 + pc4 * 4);
    }

    for (int kc = 0; kc < 96; kc++) {
        float* dA = sm + (kc & 1) * ATTN_ABUF;
        float* dB = sm + 2 * ATTN_ABUF + (kc & 1) * ATTN_ABUF;
#pragma unroll
        for (int r = 0; r < 4; r++) {
            int row = prow + 32 * r;
            *(float4*)&dA[row * SAS + pc4 * 4] = to_tf32_4(pa[r]);
            *(float4*)&dB[row * SAS + pc4 * 4] = to_tf32_4(pb[r]);
        }
        __syncthreads();
        if (kc < 95) {
            int off = ((kc + 1) >> 2) * HW_ + ((kc + 1) & 3) * 32;
#pragma unroll
            for (int r = 0; r < 4; r++) {
                int row = prow + 32 * r;
                pa[r] = *(const float4*)(Abase + off + row * 128 + pc4 * 4);
                pb[r] = *(const float4*)(Bbase + off + row * 128 + pc4 * 4);
            }
        }
#pragma unroll
        for (int k4 = 0; k4 < 4; k4++) {
            const int k0 = k4 * 8 + tig;
            uint32_t a[4][4], bf[4][2];
#pragma unroll
            for (int mt = 0; mt < 4; mt++) {
                int row = mbase + mt * 16 + g;
                a[mt][0] = __float_as_uint(dA[row * SAS + k0]);
                a[mt][1] = __float_as_uint(dA[(row + 8) * SAS + k0]);
                a[mt][2] = __float_as_uint(dA[row * SAS + k0 + 4]);
                a[mt][3] = __float_as_uint(dA[(row + 8) * SAS + k0 + 4]);
            }
#pragma unroll
            for (int nt = 0; nt < 4; nt++) {
                int col = nbase + nt * 8 + g;
                bf[nt][0] = __float_as_uint(dB[col * SAS + k0]);
                bf[nt][1] = __float_as_uint(dB[col * SAS + k0 + 4]);
            }
#pragma unroll
            for (int mt = 0; mt < 4; mt++)
#pragma unroll
                for (int nt = 0; nt < 4; nt++)
                    mma_tf32(acc[mt][nt], a[mt], bf[nt]);
        }
    }
    __syncthreads();

    const float* nI = mode ? n1w : n2h;
    const float* nJ = mode ? n2w : n1h;
    const float bias = mode ? __ldg(&pbw[hd]) : __ldg(&pbh[hd]);
    float rinv[8], cinv[8];
#pragma unroll
    for (int mt = 0; mt < 4; mt++)
#pragma unroll
        for (int half = 0; half < 2; half++) {
            int row = mbase + mt * 16 + g + half * 8;
            rinv[mt * 2 + half] = TEMP_INV / fmaxf(__ldg(&nI[bh * 128 + row]), EPS_);
        }
#pragma unroll
    for (int nt = 0; nt < 4; nt++)
#pragma unroll
        for (int cc = 0; cc < 2; cc++) {
            int col = nbase + nt * 8 + 2 * tig + cc;
            cinv[nt * 2 + cc] = 1.f / fmaxf(__ldg(&nJ[bh * 128 + col]), EPS_);
        }
    float* sc = sm;
#pragma unroll
    for (int mt = 0; mt < 4; mt++)
#pragma unroll
        for (int half = 0; half < 2; half++) {
            int row = mbase + mt * 16 + g + half * 8;
            float ri = rinv[mt * 2 + half];
#pragma unroll
            for (int nt = 0; nt < 4; nt++) {
                int col = nbase + nt * 8 + 2 * tig;
                float2 v;
                v.x = acc[mt][nt][half * 2 + 0] * (ri * cinv[nt * 2 + 0]) + bias;
                v.y = acc[mt][nt][half * 2 + 1] * (ri * cinv[nt * 2 + 1]) + bias;
                *(float2*)&sc[row * 132 + col] = v;
            }
        }
    __syncthreads();

    float* outp = (mode ? attn2 : attn1) + (size_t)bh * HW_;
    for (int r = wid; r < 128; r += 8) {
        float4 v = *(float4*)&sc[r * 132 + lane * 4];
        float m = fmaxf(fmaxf(v.x, v.y), fmaxf(v.z, v.w));
#pragma unroll
        for (int s = 16; s >= 1; s >>= 1) m = fmaxf(m, __shfl_xor_sync(0xffffffffu, m, s));
        v.x = __expf(v.x - m); v.y = __expf(v.y - m);
        v.z = __expf(v.z - m); v.w = __expf(v.w - m);
        float su = v.x + v.y + v.z + v.w;
#pragma unroll
        for (int s = 16; s >= 1; s >>= 1) su += __shfl_xor_sync(0xffffffffu, su, s);
        float inv = 1.f / su;
        v.x *= inv; v.y *= inv; v.z *= inv; v.w *= inv;
        *(float4*)&outp[r * 128 + lane * 4] = v;
    }
}

// ---------------- AV + q-residual + gated fusion via tf32 mma (no spills) ----------------
#define AVS 132
#define AV_SMEM_BYTES (2 * 128 * AVS * 4)

#define AV_STAGE(Ap, Bp) do {                                                        \
    _Pragma("unroll")                                                                \
    for (int r = 0; r < 4; r++) {                                                    \
        int row = prow + 32 * r;                                                     \
        _Pragma("unroll")                                                            \
        for (int q = 0; q < 4; q++) {                                                \
            float4 va = to_tf32_4(*(const float4*)((Ap) + row * 128 + (pc4 + 8 * q) * 4)); \
            float4 vb = to_tf32_4(*(const float4*)((Bp) + row * 128 + (pc4 + 8 * q) * 4)); \
            *(float4*)&sA[row * AVS + (pc4 + 8 * q) * 4] = va;                       \
            *(float4*)&sB[row * AVS + (pc4 + 8 * q) * 4] = vb;                       \
        }                                                                            \
    }                                                                                \
} while (0)

#define AV_MMALOOP(ACC) do {                                                         \
    _Pragma("unroll")                                                                \
    for (int k4 = 0; k4 < 16; k4++) {                                                \
        const int k0 = k4 * 8 + tig;                                                 \
        uint32_t a[4][4], bf[4][2];                                                  \
        _Pragma("unroll")                                                            \
        for (int mt = 0; mt < 4; mt++) {                                             \
            int row = mbase + mt * 16 + g;                                           \
            a[mt][0] = __float_as_uint(sA[row * AVS + k0]);                          \
            a[mt][1] = __float_as_uint(sA[(row + 8) * AVS + k0]);                    \
            a[mt][2] = __float_as_uint(sA[row * AVS + k0 + 4]);                      \
            a[mt][3] = __float_as_uint(sA[(row + 8) * AVS + k0 + 4]);                \
        }                                                                            \
        _Pragma("unroll")                                                            \
        for (int nt = 0; nt < 4; nt++) {                                             \
            int col = nbase + nt * 8 + g;                                            \
            bf[nt][0] = __float_as_uint(sB[col * AVS + k0]);                         \
            bf[nt][1] = __float_as_uint(sB[col * AVS + k0 + 4]);                     \
        }                                                                            \
        _Pragma("unroll")                                                            \
        for (int mt = 0; mt < 4; mt++)                                               \
            _Pragma("unroll")                                                        \
            for (int nt = 0; nt < 4; nt++)                                           \
                mma_tf32(ACC[mt][nt], a[mt], bf[nt]);                                \
    }                                                                                \
} while (0)

__global__ __launch_bounds__(256, 1) void av_mma_kernel(
    const float* __restrict__ o1, const float* __restrict__ o2,
    const float* __restrict__ o1t,
    const float* __restrict__ attn1, const float* __restrict__ attn2,
    const float* __restrict__ n2h, const float* __restrict__ n1w,
    const float* __restrict__ gate, float* __restrict__ fus)
{
    extern __shared__ float sm[];
    float* sA = sm;
    float* sB = sm + 128 * AVS;
    const int ch = blockIdx.x, b = blockIdx.y;
    const int hd = ch / CPH_;
    const int bh = b * 8 + hd;
    const int tid = threadIdx.x;
    const int lane = tid & 31, g = lane >> 2, tig = lane & 3;
    const int wid = tid >> 5;
    const int mbase = (wid & 1) * 64;
    const int nbase = (wid >> 1) * 32;

    const float* A1 = attn1 + (size_t)bh * HW_;
    const float* Bs1 = o1t + ((size_t)b * C_ + ch) * HW_;
    const float* A2 = o2 + ((size_t)b * C_ + ch) * HW_;
    const float* B2 = attn2 + (size_t)bh * HW_;
    const float* S1 = o1 + ((size_t)b * C_ + ch) * HW_;
    const float* S2 = A2;

    float acc1[4][4][4], acc2[4][4][4];
#pragma unroll
    for (int mt = 0; mt < 4; mt++)
#pragma unroll
        for (int nt = 0; nt < 4; nt++)
#pragma unroll
            for (int e = 0; e < 4; e++) { acc1[mt][nt][e] = 0.f; acc2[mt][nt][e] = 0.f; }

    const int prow = tid >> 3, pc4 = tid & 7;

    AV_STAGE(A1, Bs1);
    __syncthreads();
    AV_MMALOOP(acc1);
    __syncthreads();
    AV_STAGE(A2, B2);
    __syncthreads();
    AV_MMALOOP(acc2);

    const float gg = 1.f / (1.f + expf(-__ldg(&gate[0])));
    float invy[8], invx[8];
#pragma unroll
    for (int mt = 0; mt < 4; mt++)
#pragma unroll
        for (int half = 0; half < 2; half++) {
            int row = mbase + mt * 16 + g + half * 8;
            invy[mt * 2 + half] = 1.f / fmaxf(__ldg(&n2h[bh * 128 + row]), EPS_);
        }
#pragma unroll
    for (int nt = 0; nt < 4; nt++)
#pragma unroll
        for (int cc = 0; cc < 2; cc++) {
            int col = nbase + nt * 8 + 2 * tig + cc;
            invx[nt * 2 + cc] = 1.f / fmaxf(__ldg(&n1w[bh * 128 + col]), EPS_);
        }

    float* fout = fus + ((size_t)b * C_ + ch) * HW_;
#pragma unroll
    for (int mt = 0; mt < 4; mt++)
#pragma unroll
        for (int half = 0; half < 2; half++) {
            int row = mbase + mt * 16 + g + half * 8;
            float iy = invy[mt * 2 + half];
#pragma unroll
            for (int nt = 0; nt < 4; nt++) {
                int col = nbase + nt * 8 + 2 * tig;
                float2 s1v = *(const float2*)(S1 + row * 128 + col);
                float2 s2v = *(const float2*)(S2 + row * 128 + col);
                float2 o;
                o.x = gg * (acc1[mt][nt][half * 2 + 0] + s2v.x * iy)
                    + (1.f - gg) * (acc2[mt][nt][half * 2 + 0] + s1v.x * invx[nt * 2 + 0]);
                o.y = gg * (acc1[mt][nt][half * 2 + 1] + s2v.y * iy)
                    + (1.f - gg) * (acc2[mt][nt][half * 2 + 1] + s1v.y * invx[nt * 2 + 1]);
                *(float2*)(fout + row * 128 + col) = o;
            }
        }
}

// ---------------- host launcher ----------------
extern "C" void kernel_launch(void* const* d_in, const int* in_sizes, int n_in,
                              void* d_out, int out_size)
{
    const float* x1  = (const float*)d_in[0];
    const float* x2  = (const float*)d_in[1];
    const float* Wp  = (const float*)d_in[2];
    const float* bp  = (const float*)d_in[3];
    const float* gate= (const float*)d_in[4];
    const float* pbh = (const float*)d_in[5];
    const float* pbw = (const float*)d_in[6];
    const float* Wm1 = (const float*)d_in[7];
    const float* bm1 = (const float*)d_in[8];
    const float* Wm2 = (const float*)d_in[9];
    const float* bm2 = (const float*)d_in[10];
    float* out = (float*)d_out;

    float *p_o1, *p_o2, *p_o1t, *p_o2t, *p_fus, *p_cl, *p_a1, *p_a2;
    float *p_n1h, *p_n2h, *p_n1w, *p_n2w;
    cudaGetSymbolAddress((void**)&p_o1, g_o1);
    cudaGetSymbolAddress((void**)&p_o2, g_o2);
    cudaGetSymbolAddress((void**)&p_o1t, g_o1t);
    cudaGetSymbolAddress((void**)&p_o2t, g_o2t);
    cudaGetSymbolAddress((void**)&p_fus, g_fus);
    cudaGetSymbolAddress((void**)&p_cl, g_cl);
    cudaGetSymbolAddress((void**)&p_a1, g_attn1);
    cudaGetSymbolAddress((void**)&p_a2, g_attn2);
    cudaGetSymbolAddress((void**)&p_n1h, g_n1h);
    cudaGetSymbolAddress((void**)&p_n2h, g_n2h);
    cudaGetSymbolAddress((void**)&p_n1w, g_n1w);
    cudaGetSymbolAddress((void**)&p_n2w, g_n2w);

    cudaFuncSetAttribute(conv_mma_kernel, cudaFuncAttributeMaxDynamicSharedMemorySize, SMEM_BYTES);
    cudaFuncSetAttribute(attn_mma_kernel, cudaFuncAttributeMaxDynamicSharedMemorySize, ATTN_SMEM_BYTES);
    cudaFuncSetAttribute(av_mma_kernel, cudaFuncAttributeMaxDynamicSharedMemorySize, AV_SMEM_BYTES);

    dim3 tGrid(HW_ / 32, C_ / 32, B_);
    dim3 tBlk(32, 8);
    dim3 rGrid(16, C_, B_);

    transpose_cf_cl_kernel<<<tGrid, tBlk>>>(x1, p_cl);
    conv_mma_kernel<<<NTILES_, 256, SMEM_BYTES>>>(p_cl, Wp, bp, p_o1, 0, nullptr, nullptr);
    transpose_cf_cl_kernel<<<tGrid, tBlk>>>(x2, p_cl);
    conv_mma_kernel<<<NTILES_, 256, SMEM_BYTES>>>(p_cl, Wp, bp, p_o2, 0, nullptr, nullptr);

    norm_kernel<<<dim3(B_ * HEADS_, 2), 256>>>(p_o1, p_o2, p_n1h, p_n1w, p_n2h, p_n2w);
    repack_kernel<<<rGrid, tBlk>>>(p_o1, p_o1t);
    repack_kernel<<<rGrid, tBlk>>>(p_o2, p_o2t);

    attn_mma_kernel<<<dim3(B_ * HEADS_, 2), 256, ATTN_SMEM_BYTES>>>(
        p_o1, p_o2, p_o1t, p_o2t, p_n1h, p_n2h, p_n1w, p_n2w, pbh, pbw, p_a1, p_a2);

    av_mma_kernel<<<dim3(C_, B_), 256, AV_SMEM_BYTES>>>(
        p_o1, p_o2, p_o1t, p_a1, p_a2, p_n2h, p_n1w, gate, p_fus);

    transpose_cf_cl_kernel<<<tGrid, tBlk>>>(p_fus, p_cl);
    conv_mma_kernel<<<NTILES_, 256, SMEM_BYTES>>>(p_cl, Wp, bp, p_o1, 2, nullptr, nullptr);
    conv_mma_kernel<<<NTILES_, 256, SMEM_BYTES>>>(p_o1, Wm1, bm1, p_o2, 3, nullptr, nullptr);
    conv_mma_kernel<<<NTILES_, 256, SMEM_BYTES>>>(p_o2, Wm2, bm2, out, 0, x1, x2);

    (void)in_sizes; (void)n_in; (void)out_size;
}

// round 6
// speedup vs baseline: 1.7701x; 1.0771x over previous
#include <cuda_runtime.h>
#include <math.h>
#include <stdint.h>

#define B_ 8
#define C_ 192
#define H_ 128
#define W_ 128
#define HW_ 16384
#define HEADS_ 8
#define CPH_ 24
#define TEMP_INV 100.0f
#define EPS_ 1e-12f

#define NPIX_ (B_ * HW_)
#define NTILES_ (NPIX_ / 128)
#define TILE_ELEMS (128 * C_)

// ---------------- scratch ----------------
__device__ float g_o1[(size_t)B_ * C_ * HW_];
__device__ float g_o2[(size_t)B_ * C_ * HW_];
__device__ float g_o1t[(size_t)B_ * C_ * HW_];
__device__ float g_o2t[(size_t)B_ * C_ * HW_];
__device__ float g_fus[(size_t)B_ * C_ * HW_];
__device__ float g_cl[(size_t)NPIX_ * C_];
__device__ float g_attn1[(size_t)B_ * HEADS_ * HW_];
__device__ float g_attn2[(size_t)B_ * HEADS_ * HW_];
__device__ float g_n1h[B_ * HEADS_ * H_];
__device__ float g_n2h[B_ * HEADS_ * H_];
__device__ float g_n1w[B_ * HEADS_ * W_];
__device__ float g_n2w[B_ * HEADS_ * W_];

__device__ __forceinline__ float to_tf32(float x) {
    uint32_t u; asm("cvt.rna.tf32.f32 %0, %1;" : "=r"(u) : "f"(x));
    return __uint_as_float(u);
}
__device__ __forceinline__ float4 to_tf32_4(float4 v) {
    v.x = to_tf32(v.x); v.y = to_tf32(v.y); v.z = to_tf32(v.z); v.w = to_tf32(v.w);
    return v;
}

__device__ __forceinline__ void mma_tf32(float* c, const uint32_t* a, const uint32_t* b) {
    asm volatile(
        "mma.sync.aligned.m16n8k8.row.col.f32.tf32.tf32.f32 "
        "{%0,%1,%2,%3}, {%4,%5,%6,%7}, {%8,%9}, {%0,%1,%2,%3};"
        : "+f"(c[0]), "+f"(c[1]), "+f"(c[2]), "+f"(c[3])
        : "r"(a[0]), "r"(a[1]), "r"(a[2]), "r"(a[3]), "r"(b[0]), "r"(b[1]));
}

// ---------------- transpose: channel-first -> channel-last, tf32-rounded ----
__global__ __launch_bounds__(256) void transpose_cf_cl_kernel(
    const float* __restrict__ in, float* __restrict__ out)
{
    __shared__ float t[32][33];
    const int b = blockIdx.z;
    const int p0 = blockIdx.x * 32;
    const int c0 = blockIdx.y * 32;
    const int tx = threadIdx.x, ty = threadIdx.y;
    const float* ib = in + (size_t)b * C_ * HW_;
    float* ob = out + (size_t)b * HW_ * C_;
#pragma unroll
    for (int i = ty; i < 32; i += 8)
        t[i][tx] = ib[(size_t)(c0 + i) * HW_ + p0 + tx];
    __syncthreads();
#pragma unroll
    for (int i = ty; i < 32; i += 8)
        ob[(size_t)(p0 + i) * C_ + c0 + tx] = to_tf32(t[tx][i]);
}

// ---------------- repack: per (b,c) [y][x] -> [x][y] ----------------
__global__ __launch_bounds__(256) void repack_kernel(
    const float* __restrict__ in, float* __restrict__ out)
{
    __shared__ float t[32][33];
    const int c = blockIdx.y, b = blockIdx.z;
    const int x0 = (blockIdx.x & 3) * 32, y0 = (blockIdx.x >> 2) * 32;
    const int tx = threadIdx.x, ty = threadIdx.y;
    const float* ib = in + ((size_t)b * C_ + c) * HW_;
    float* ob = out + ((size_t)b * C_ + c) * HW_;
#pragma unroll
    for (int i = ty; i < 32; i += 8)
        t[i][tx] = ib[(y0 + i) * 128 + x0 + tx];
    __syncthreads();
#pragma unroll
    for (int i = ty; i < 32; i += 8)
        ob[(x0 + i) * 128 + y0 + tx] = t[tx][i];
}

// ---------------- conv1x1 via mma.sync tf32, 512 thr, double-buffered ----------------
#define SAS 36
#define CONV_ABUF (128 * SAS)
#define CONV_WBUF (192 * SAS)
#define CONV_SMEM_FLOATS (128 * 196)
#define SMEM_BYTES (CONV_SMEM_FLOATS * 4)

__global__ __launch_bounds__(512, 1) void conv_mma_kernel(
    const float* __restrict__ Acl, const float* __restrict__ Wt,
    const float* __restrict__ bias, float* __restrict__ out,
    int flags, const float* __restrict__ r1, const float* __restrict__ r2)
{
    extern __shared__ float sm[];
    const int tid = threadIdx.x;
    const int lane = tid & 31;
    const int g = lane >> 2;
    const int tig = lane & 3;
    const int wid = tid >> 5;                 // 0..15
    const int mbase = (wid & 3) * 32;         // 4 m-groups of 32
    const int nbase = (wid >> 2) * 48;        // 4 n-groups of 48
    const int t = blockIdx.x;
    const float* Arow = Acl + (size_t)t * TILE_ELEMS;

    float c[2][6][4];
#pragma unroll
    for (int mt = 0; mt < 2; mt++)
#pragma unroll
        for (int nt = 0; nt < 6; nt++)
#pragma unroll
            for (int r = 0; r < 4; r++) c[mt][nt][r] = 0.f;

    float4 pa[2], pw[3];
#pragma unroll
    for (int r = 0; r < 2; r++) {
        int f = tid + 512 * r;
        int pix = f >> 3, c4 = f & 7;
        pa[r] = *(const float4*)(Arow + (size_t)pix * C_ + c4 * 4);
    }
#pragma unroll
    for (int r = 0; r < 3; r++) {
        int f = tid + 512 * r;
        int o = f >> 3, c4 = f & 7;
        pw[r] = *(const float4*)(Wt + (size_t)o * C_ + c4 * 4);
    }

    for (int kc = 0; kc < 6; kc++) {
        float* dA = sm + (kc & 1) * CONV_ABUF;
        float* dW = sm + 2 * CONV_ABUF + (kc & 1) * CONV_WBUF;
#pragma unroll
        for (int r = 0; r < 2; r++) {
            int f = tid + 512 * r;
            int pix = f >> 3, c4 = f & 7;
            *(float4*)&dA[pix * SAS + c4 * 4] = pa[r];
        }
#pragma unroll
        for (int r = 0; r < 3; r++) {
            int f = tid + 512 * r;
            int o = f >> 3, c4 = f & 7;
            *(float4*)&dW[o * SAS + c4 * 4] = to_tf32_4(pw[r]);
        }
        __syncthreads();
        if (kc < 5) {
            int ko = (kc + 1) * 32;
#pragma unroll
            for (int r = 0; r < 2; r++) {
                int f = tid + 512 * r;
                int pix = f >> 3, c4 = f & 7;
                pa[r] = *(const float4*)(Arow + (size_t)pix * C_ + ko + c4 * 4);
            }
#pragma unroll
            for (int r = 0; r < 3; r++) {
                int f = tid + 512 * r;
                int o = f >> 3, c4 = f & 7;
                pw[r] = *(const float4*)(Wt + (size_t)o * C_ + ko + c4 * 4);
            }
        }
#pragma unroll
        for (int kk = 0; kk < 4; kk++) {
            const int k0 = kk * 8 + tig;
            uint32_t a[2][4], b[6][2];
#pragma unroll
            for (int mt = 0; mt < 2; mt++) {
                int row = mbase + mt * 16 + g;
                a[mt][0] = __float_as_uint(dA[row * SAS + k0]);
                a[mt][1] = __float_as_uint(dA[(row + 8) * SAS + k0]);
                a[mt][2] = __float_as_uint(dA[row * SAS + k0 + 4]);
                a[mt][3] = __float_as_uint(dA[(row + 8) * SAS + k0 + 4]);
            }
#pragma unroll
            for (int nt = 0; nt < 6; nt++) {
                int col = nbase + nt * 8 + g;
                b[nt][0] = __float_as_uint(dW[col * SAS + k0]);
                b[nt][1] = __float_as_uint(dW[col * SAS + k0 + 4]);
            }
#pragma unroll
            for (int mt = 0; mt < 2; mt++)
#pragma unroll
                for (int nt = 0; nt < 6; nt++)
                    mma_tf32(c[mt][nt], a[mt], b[nt]);
        }
    }
    __syncthreads();

    const int gelu = flags & 1;
    float bv[6][2];
#pragma unroll
    for (int nt = 0; nt < 6; nt++) {
        int o = nbase + nt * 8 + 2 * tig;
        bv[nt][0] = __ldg(&bias[o]);
        bv[nt][1] = __ldg(&bias[o + 1]);
    }

    if (flags & 2) {
        float* sO = sm;
#pragma unroll
        for (int mt = 0; mt < 2; mt++) {
            int row0 = mbase + mt * 16 + g;
#pragma unroll
            for (int nt = 0; nt < 6; nt++) {
                int o = nbase + nt * 8 + 2 * tig;
#pragma unroll
                for (int half = 0; half < 2; half++) {
                    int row = row0 + half * 8;
                    float v0 = c[mt][nt][half * 2 + 0] + bv[nt][0];
                    float v1 = c[mt][nt][half * 2 + 1] + bv[nt][1];
                    if (gelu) {
                        v0 = 0.5f * v0 * (1.0f + erff(v0 * 0.70710678118654752f));
                        v1 = 0.5f * v1 * (1.0f + erff(v1 * 0.70710678118654752f));
                    }
                    float2 w = {to_tf32(v0), to_tf32(v1)};
                    *(float2*)&sO[row * 196 + o] = w;
                }
            }
        }
        __syncthreads();
        float* ob = out + (size_t)t * TILE_ELEMS;
#pragma unroll
        for (int r = 0; r < 12; r++) {
            int f = tid + 512 * r;
            int pix = f / 48, c4 = f % 48;
            *(float4*)(ob + (size_t)pix * C_ + c4 * 4) = *(float4*)&sO[pix * 196 + c4 * 4];
        }
    } else {
        const int pg0 = t << 7;
        const int b = pg0 >> 14;
        const int p0 = pg0 & (HW_ - 1);
#pragma unroll
        for (int mt = 0; mt < 2; mt++) {
            int row0 = mbase + mt * 16 + g;
#pragma unroll
            for (int nt = 0; nt < 6; nt++) {
                int o = nbase + nt * 8 + 2 * tig;
#pragma unroll
                for (int half = 0; half < 2; half++) {
                    int row = row0 + half * 8;
#pragma unroll
                    for (int cc = 0; cc < 2; cc++) {
                        float v = c[mt][nt][half * 2 + cc] + bv[nt][cc];
                        if (gelu) v = 0.5f * v * (1.0f + erff(v * 0.70710678118654752f));
                        size_t idx = ((size_t)(b * C_ + o + cc) << 14) + p0 + row;
                        if (r1) v += __ldg(&r1[idx]) + __ldg(&r2[idx]);
                        out[idx] = v;
                    }
                }
            }
        }
    }
}

// ---------------- norms ----------------
__global__ __launch_bounds__(256) void norm_kernel(
    const float* __restrict__ o1, const float* __restrict__ o2,
    float* __restrict__ n1h, float* __restrict__ n1w,
    float* __restrict__ n2h, float* __restrict__ n2w)
{
    const int bh = blockIdx.x;
    const int src = blockIdx.y;
    const int tid = threadIdx.x;
    const float* base = (src ? o2 : o1) + ((size_t)(bh >> 3) * C_ + (bh & 7) * CPH_) * HW_;

    __shared__ float sRow[128];
    __shared__ float sColA[256];
    if (tid < 128) sRow[tid] = 0.f;
    __syncthreads();

    float colAcc = 0.f;
    for (int idx = tid; idx < CPH_ * HW_; idx += 256) {
        float v = base[idx];
        v *= v;
        colAcc += v;
        float rv = v;
#pragma unroll
        for (int s = 16; s >= 1; s >>= 1) rv += __shfl_xor_sync(0xffffffffu, rv, s);
        if ((tid & 31) == 0) atomicAdd(&sRow[(idx >> 7) & 127], rv);
    }
    sColA[tid] = colAcc;
    __syncthreads();
    if (tid < 128) {
        float cs = sColA[tid] + sColA[tid + 128];
        float rs = sRow[tid];
        if (src) { n2h[bh * 128 + tid] = sqrtf(rs); n2w[bh * 128 + tid] = sqrtf(cs); }
        else     { n1h[bh * 128 + tid] = sqrtf(rs); n1w[bh * 128 + tid] = sqrtf(cs); }
    }
}

// ---------------- attention via tf32 mma, 512 thr, K-chunk 64, double-buffered ----------------
#define AAS 68
#define ATTN_ABUF (128 * AAS)                    // 8704 floats
#define ATTN_SMEM_BYTES (4 * ATTN_ABUF * 4)      // 139264

__global__ __launch_bounds__(512, 1) void attn_mma_kernel(
    const float* __restrict__ o1, const float* __restrict__ o2,
    const float* __restrict__ o1t, const float* __restrict__ o2t,
    const float* __restrict__ n1h, const float* __restrict__ n2h,
    const float* __restrict__ n1w, const float* __restrict__ n2w,
    const float* __restrict__ pbh, const float* __restrict__ pbw,
    float* __restrict__ attn1, float* __restrict__ attn2)
{
    extern __shared__ float sm[];
    const int bh = blockIdx.x;
    const int mode = blockIdx.y;
    const int hd = bh & 7, b = bh >> 3;
    const int tid = threadIdx.x;
    const int lane = tid & 31, g = lane >> 2, tig = lane & 3;
    const int wid = tid >> 5;
    const int mbase = (wid & 3) * 32;
    const int nbase = (wid >> 2) * 32;
    const float* Abase = (mode ? o1t : o2) + ((size_t)b * C_ + hd * CPH_) * HW_;
    const float* Bbase = (mode ? o2t : o1) + ((size_t)b * C_ + hd * CPH_) * HW_;

    float acc[2][4][4];
#pragma unroll
    for (int mt = 0; mt < 2; mt++)
#pragma unroll
        for (int nt = 0; nt < 4; nt++)
#pragma unroll
            for (int e = 0; e < 4; e++) acc[mt][nt][e] = 0.f;

    const int prow = tid >> 4, pc4 = tid & 15;   // f = tid + 512*r: row=f>>4, c4=f&15
    float4 pa[4], pb[4];
#pragma unroll
    for (int r = 0; r < 4; r++) {
        int row = prow + 32 * r;
        pa[r] = *(const float4*)(Abase + row * 128 + pc4 * 4);
        pb[r] = *(const float4*)(Bbase + row * 128 + pc4 * 4);
    }

    for (int kc = 0; kc < 48; kc++) {
        float* dA = sm + (kc & 1) * ATTN_ABUF;
        float* dB = sm + 2 * ATTN_ABUF + (kc & 1) * ATTN_ABUF;
#pragma unroll
        for (int r = 0; r < 4; r++) {
            int row = prow + 32 * r;
            *(float4*)&dA[row * AAS + pc4 * 4] = to_tf32_4(pa[r]);
            *(float4*)&dB[row * AAS + pc4 * 4] = to_tf32_4(pb[r]);
        }
        __syncthreads();
        if (kc < 47) {
            int off = ((kc + 1) >> 1) * HW_ + ((kc + 1) & 1) * 64;
#pragma unroll
            for (int r = 0; r < 4; r++) {
                int row = prow + 32 * r;
                pa[r] = *(const float4*)(Abase + off + row * 128 + pc4 * 4);
                pb[r] = *(const float4*)(Bbase + off + row * 128 + pc4 * 4);
            }
        }
#pragma unroll
        for (int k4 = 0; k4 < 8; k4++) {
            const int k0 = k4 * 8 + tig;
            uint32_t a[2][4], bf[4][2];
#pragma unroll
            for (int mt = 0; mt < 2; mt++) {
                int row = mbase + mt * 16 + g;
                a[mt][0] = __float_as_uint(dA[row * AAS + k0]);
                a[mt][1] = __float_as_uint(dA[(row + 8) * AAS + k0]);
                a[mt][2] = __float_as_uint(dA[row * AAS + k0 + 4]);
                a[mt][3] = __float_as_uint(dA[(row + 8) * AAS + k0 + 4]);
            }
#pragma unroll
            for (int nt = 0; nt < 4; nt++) {
                int col = nbase + nt * 8 + g;
                bf[nt][0] = __float_as_uint(dB[col * AAS + k0]);
                bf[nt][1] = __float_as_uint(dB[col * AAS + k0 + 4]);
            }
#pragma unroll
            for (int mt = 0; mt < 2; mt++)
#pragma unroll
                for (int nt = 0; nt < 4; nt++)
                    mma_tf32(acc[mt][nt], a[mt], bf[nt]);
        }
        __syncthreads();
    }

    const float* nI = mode ? n1w : n2h;
    const float* nJ = mode ? n2w : n1h;
    const float bias = mode ? __ldg(&pbw[hd]) : __ldg(&pbh[hd]);
    float rinv[4], cinv[8];
#pragma unroll
    for (int mt = 0; mt < 2; mt++)
#pragma unroll
        for (int half = 0; half < 2; half++) {
            int row = mbase + mt * 16 + g + half * 8;
            rinv[mt * 2 + half] = TEMP_INV / fmaxf(__ldg(&nI[bh * 128 + row]), EPS_);
        }
#pragma unroll
    for (int nt = 0; nt < 4; nt++)
#pragma unroll
        for (int cc = 0; cc < 2; cc++) {
            int col = nbase + nt * 8 + 2 * tig + cc;
            cinv[nt * 2 + cc] = 1.f / fmaxf(__ldg(&nJ[bh * 128 + col]), EPS_);
        }
    float* sc = sm;   // [128][132]
#pragma unroll
    for (int mt = 0; mt < 2; mt++)
#pragma unroll
        for (int half = 0; half < 2; half++) {
            int row = mbase + mt * 16 + g + half * 8;
            float ri = rinv[mt * 2 + half];
#pragma unroll
            for (int nt = 0; nt < 4; nt++) {
                int col = nbase + nt * 8 + 2 * tig;
                float2 v;
                v.x = acc[mt][nt][half * 2 + 0] * (ri * cinv[nt * 2 + 0]) + bias;
                v.y = acc[mt][nt][half * 2 + 1] * (ri * cinv[nt * 2 + 1]) + bias;
                *(float2*)&sc[row * 132 + col] = v;
            }
        }
    __syncthreads();

    float* outp = (mode ? attn2 : attn1) + (size_t)bh * HW_;
    for (int r = wid; r < 128; r += 16) {
        float4 v = *(float4*)&sc[r * 132 + lane * 4];
        float m = fmaxf(fmaxf(v.x, v.y), fmaxf(v.z, v.w));
#pragma unroll
        for (int s = 16; s >= 1; s >>= 1) m = fmaxf(m, __shfl_xor_sync(0xffffffffu, m, s));
        v.x = __expf(v.x - m); v.y = __expf(v.y - m);
        v.z = __expf(v.z - m); v.w = __expf(v.w - m);
        float su = v.x + v.y + v.z + v.w;
#pragma unroll
        for (int s = 16; s >= 1; s >>= 1) su += __shfl_xor_sync(0xffffffffu, su, s);
        float inv = 1.f / su;
        v.x *= inv; v.y *= inv; v.z *= inv; v.w *= inv;
        *(float4*)&outp[r * 128 + lane * 4] = v;
    }
}

// ---------------- AV + q-residual + gated fusion via tf32 mma, 512 thr ----------------
#define AVS 132
#define AV_SMEM_BYTES (2 * 128 * AVS * 4)

#define AV_STAGE(Ap, Bp) do {                                                        \
    _Pragma("unroll")                                                                \
    for (int r = 0; r < 8; r++) {                                                    \
        int f = tid + 512 * r;                                                       \
        int row = f >> 5, c4 = f & 31;                                               \
        float4 va = to_tf32_4(*(const float4*)((Ap) + row * 128 + c4 * 4));          \
        float4 vb = to_tf32_4(*(const float4*)((Bp) + row * 128 + c4 * 4));          \
        *(float4*)&sA[row * AVS + c4 * 4] = va;                                      \
        *(float4*)&sB[row * AVS + c4 * 4] = vb;                                      \
    }                                                                                \
} while (0)

#define AV_MMALOOP(ACC) do {                                                         \
    _Pragma("unroll")                                                                \
    for (int k4 = 0; k4 < 16; k4++) {                                                \
        const int k0 = k4 * 8 + tig;                                                 \
        uint32_t a[2][4], bf[4][2];                                                  \
        _Pragma("unroll")                                                            \
        for (int mt = 0; mt < 2; mt++) {                                             \
            int row = mbase + mt * 16 + g;                                           \
            a[mt][0] = __float_as_uint(sA[row * AVS + k0]);                          \
            a[mt][1] = __float_as_uint(sA[(row + 8) * AVS + k0]);                    \
            a[mt][2] = __float_as_uint(sA[row * AVS + k0 + 4]);                      \
            a[mt][3] = __float_as_uint(sA[(row + 8) * AVS + k0 + 4]);                \
        }                                                                            \
        _Pragma("unroll")                                                            \
        for (int nt = 0; nt < 4; nt++) {                                             \
            int col = nbase + nt * 8 + g;                                            \
            bf[nt][0] = __float_as_uint(sB[col * AVS + k0]);                         \
            bf[nt][1] = __float_as_uint(sB[col * AVS + k0 + 4]);                     \
        }                                                                            \
        _Pragma("unroll")                                                            \
        for (int mt = 0; mt < 2; mt++)                                               \
            _Pragma("unroll")                                                        \
            for (int nt = 0; nt < 4; nt++)                                           \
                mma_tf32(ACC[mt][nt], a[mt], bf[nt]);                                \
    }                                                                                \
} while (0)

__global__ __launch_bounds__(512, 1) void av_mma_kernel(
    const float* __restrict__ o1, const float* __restrict__ o2,
    const float* __restrict__ o1t,
    const float* __restrict__ attn1, const float* __restrict__ attn2,
    const float* __restrict__ n2h, const float* __restrict__ n1w,
    const float* __restrict__ gate, float* __restrict__ fus)
{
    extern __shared__ float sm[];
    float* sA = sm;
    float* sB = sm + 128 * AVS;
    const int ch = blockIdx.x, b = blockIdx.y;
    const int hd = ch / CPH_;
    const int bh = b * 8 + hd;
    const int tid = threadIdx.x;
    const int lane = tid & 31, g = lane >> 2, tig = lane & 3;
    const int wid = tid >> 5;
    const int mbase = (wid & 3) * 32;
    const int nbase = (wid >> 2) * 32;

    const float* A1 = attn1 + (size_t)bh * HW_;
    const float* Bs1 = o1t + ((size_t)b * C_ + ch) * HW_;
    const float* A2 = o2 + ((size_t)b * C_ + ch) * HW_;
    const float* B2 = attn2 + (size_t)bh * HW_;
    const float* S1 = o1 + ((size_t)b * C_ + ch) * HW_;
    const float* S2 = A2;

    float acc1[2][4][4], acc2[2][4][4];
#pragma unroll
    for (int mt = 0; mt < 2; mt++)
#pragma unroll
        for (int nt = 0; nt < 4; nt++)
#pragma unroll
            for (int e = 0; e < 4; e++) { acc1[mt][nt][e] = 0.f; acc2[mt][nt][e] = 0.f; }

    AV_STAGE(A1, Bs1);
    __syncthreads();
    AV_MMALOOP(acc1);
    __syncthreads();
    AV_STAGE(A2, B2);
    __syncthreads();
    AV_MMALOOP(acc2);

    const float gg = 1.f / (1.f + expf(-__ldg(&gate[0])));
    float invy[4], invx[8];
#pragma unroll
    for (int mt = 0; mt < 2; mt++)
#pragma unroll
        for (int half = 0; half < 2; half++) {
            int row = mbase + mt * 16 + g + half * 8;
            invy[mt * 2 + half] = 1.f / fmaxf(__ldg(&n2h[bh * 128 + row]), EPS_);
        }
#pragma unroll
    for (int nt = 0; nt < 4; nt++)
#pragma unroll
        for (int cc = 0; cc < 2; cc++) {
            int col = nbase + nt * 8 + 2 * tig + cc;
            invx[nt * 2 + cc] = 1.f / fmaxf(__ldg(&n1w[bh * 128 + col]), EPS_);
        }

    float* fout = fus + ((size_t)b * C_ + ch) * HW_;
#pragma unroll
    for (int mt = 0; mt < 2; mt++)
#pragma unroll
        for (int half = 0; half < 2; half++) {
            int row = mbase + mt * 16 + g + half * 8;
            float iy = invy[mt * 2 + half];
#pragma unroll
            for (int nt = 0; nt < 4; nt++) {
                int col = nbase + nt * 8 + 2 * tig;
                float2 s1v = *(const float2*)(S1 + row * 128 + col);
                float2 s2v = *(const float2*)(S2 + row * 128 + col);
                float2 o;
                o.x = gg * (acc1[mt][nt][half * 2 + 0] + s2v.x * iy)
                    + (1.f - gg) * (acc2[mt][nt][half * 2 + 0] + s1v.x * invx[nt * 2 + 0]);
                o.y = gg * (acc1[mt][nt][half * 2 + 1] + s2v.y * iy)
                    + (1.f - gg) * (acc2[mt][nt][half * 2 + 1] + s1v.y * invx[nt * 2 + 1]);
                *(float2*)(fout + row * 128 + col) = o;
            }
        }
}

// ---------------- host launcher ----------------
extern "C" void kernel_launch(void* const* d_in, const int* in_sizes, int n_in,
                              void* d_out, int out_size)
{
    const float* x1  = (const float*)d_in[0];
    const float* x2  = (const float*)d_in[1];
    const float* Wp  = (const float*)d_in[2];
    const float* bp  = (const float*)d_in[3];
    const float* gate= (const float*)d_in[4];
    const float* pbh = (const float*)d_in[5];
    const float* pbw = (const float*)d_in[6];
    const float* Wm1 = (const float*)d_in[7];
    const float* bm1 = (const float*)d_in[8];
    const float* Wm2 = (const float*)d_in[9];
    const float* bm2 = (const float*)d_in[10];
    float* out = (float*)d_out;

    float *p_o1, *p_o2, *p_o1t, *p_o2t, *p_fus, *p_cl, *p_a1, *p_a2;
    float *p_n1h, *p_n2h, *p_n1w, *p_n2w;
    cudaGetSymbolAddress((void**)&p_o1, g_o1);
    cudaGetSymbolAddress((void**)&p_o2, g_o2);
    cudaGetSymbolAddress((void**)&p_o1t, g_o1t);
    cudaGetSymbolAddress((void**)&p_o2t, g_o2t);
    cudaGetSymbolAddress((void**)&p_fus, g_fus);
    cudaGetSymbolAddress((void**)&p_cl, g_cl);
    cudaGetSymbolAddress((void**)&p_a1, g_attn1);
    cudaGetSymbolAddress((void**)&p_a2, g_attn2);
    cudaGetSymbolAddress((void**)&p_n1h, g_n1h);
    cudaGetSymbolAddress((void**)&p_n2h, g_n2h);
    cudaGetSymbolAddress((void**)&p_n1w, g_n1w);
    cudaGetSymbolAddress((void**)&p_n2w, g_n2w);

    cudaFuncSetAttribute(conv_mma_kernel, cudaFuncAttributeMaxDynamicSharedMemorySize, SMEM_BYTES);
    cudaFuncSetAttribute(attn_mma_kernel, cudaFuncAttributeMaxDynamicSharedMemorySize, ATTN_SMEM_BYTES);
    cudaFuncSetAttribute(av_mma_kernel, cudaFuncAttributeMaxDynamicSharedMemorySize, AV_SMEM_BYTES);

    dim3 tGrid(HW_ / 32, C_ / 32, B_);
    dim3 tBlk(32, 8);
    dim3 rGrid(16, C_, B_);

    transpose_cf_cl_kernel<<<tGrid, tBlk>>>(x1, p_cl);
    conv_mma_kernel<<<NTILES_, 512, SMEM_BYTES>>>(p_cl, Wp, bp, p_o1, 0, nullptr, nullptr);
    transpose_cf_cl_kernel<<<tGrid, tBlk>>>(x2, p_cl);
    conv_mma_kernel<<<NTILES_, 512, SMEM_BYTES>>>(p_cl, Wp, bp, p_o2, 0, nullptr, nullptr);

    norm_kernel<<<dim3(B_ * HEADS_, 2), 256>>>(p_o1, p_o2, p_n1h, p_n1w, p_n2h, p_n2w);
    repack_kernel<<<rGrid, tBlk>>>(p_o1, p_o1t);
    repack_kernel<<<rGrid, tBlk>>>(p_o2, p_o2t);

    attn_mma_kernel<<<dim3(B_ * HEADS_, 2), 512, ATTN_SMEM_BYTES>>>(
        p_o1, p_o2, p_o1t, p_o2t, p_n1h, p_n2h, p_n1w, p_n2w, pbh, pbw, p_a1, p_a2);

    av_mma_kernel<<<dim3(C_, B_), 512, AV_SMEM_BYTES>>>(
        p_o1, p_o2, p_o1t, p_a1, p_a2, p_n2h, p_n1w, gate, p_fus);

    transpose_cf_cl_kernel<<<tGrid, tBlk>>>(p_fus, p_cl);
    conv_mma_kernel<<<NTILES_, 512, SMEM_BYTES>>>(p_cl, Wp, bp, p_o1, 2, nullptr, nullptr);
    conv_mma_kernel<<<NTILES_, 512, SMEM_BYTES>>>(p_o1, Wm1, bm1, p_o2, 3, nullptr, nullptr);
    conv_mma_kernel<<<NTILES_, 512, SMEM_BYTES>>>(p_o2, Wm2, bm2, out, 0, x1, x2);

    (void)in_sizes; (void)n_in; (void)out_size;
}